// round 11
// baseline (speedup 1.0000x reference)
#include <cuda_runtime.h>
#include <math.h>
#include <stdint.h>

// Problem constants
#define B_    4
#define N_    1024
#define DIM_  768
#define H_    12
#define KV_   4
#define D_    64
#define SIDE_ 32
#define WIN_  8
#define REP_  (H_ / KV_)       // 3
#define M_ROWS (B_ * N_)       // 4096

// Fused projection layout: [row][2560] = q(0..1535) | k(1536..2047) | v1(2048..2303) | v2(2304..2559)
#define PROJ_N 2560
#define OFF_K  1536
#define OFF_V1 2048

// ---------------------------------------------------------------------------
// Scratch
// ---------------------------------------------------------------------------
__device__ float g_x   [M_ROWS * DIM_];
__device__ float g_wqkv[PROJ_N * DIM_];
__device__ float g_wo  [DIM_ * DIM_];
__device__ float g_proj[M_ROWS * PROJ_N];
__device__ float g_od  [2 * M_ROWS * DIM_];   // per-side normalized O
__device__ float g_ctx [M_ROWS * DIM_];

// ---------------------------------------------------------------------------
// PTX helpers
// ---------------------------------------------------------------------------
__device__ __forceinline__ float to_tf32(float x) {
    asm("cvt.rna.tf32.f32 %0, %0;" : "+f"(x));
    return x;
}
__device__ __forceinline__ uint32_t f2tf(float x) {
    asm("cvt.rna.tf32.f32 %0, %0;" : "+f"(x));
    return __float_as_uint(x);
}
__device__ __forceinline__ void mma_tf32(float* c, const uint32_t* a, const uint32_t* b) {
    asm volatile(
        "mma.sync.aligned.m16n8k8.row.col.f32.tf32.tf32.f32 "
        "{%0,%1,%2,%3}, {%4,%5,%6,%7}, {%8,%9}, {%0,%1,%2,%3};\n"
        : "+f"(c[0]), "+f"(c[1]), "+f"(c[2]), "+f"(c[3])
        : "r"(a[0]), "r"(a[1]), "r"(a[2]), "r"(a[3]), "r"(b[0]), "r"(b[1]));
}
__device__ __forceinline__ void cpa16(float* dst, const float* src) {
    unsigned u = (unsigned)__cvta_generic_to_shared(dst);
    asm volatile("cp.async.cg.shared.global [%0], [%1], 16;\n" :: "r"(u), "l"(src));
}
// exp(x) for |x| <= 0.125: degree-4 Taylor, max rel err ~2.5e-7, pure FMA.
__device__ __forceinline__ float exp_small(float x) {
    float r = fmaf(x, 0.041666667f, 0.16666667f);
    r = fmaf(x, r, 0.5f);
    r = fmaf(x, r, 1.0f);
    r = fmaf(x, r, 1.0f);
    return r;
}

// ---------------------------------------------------------------------------
// Prep: tf32-round x, concat+round weights (float4 per thread).
// ---------------------------------------------------------------------------
#define PREP_TOTAL 1425408

__global__ __launch_bounds__(256)
void prep_tf32(const float* __restrict__ x,  const float* __restrict__ Wq,
               const float* __restrict__ Wk, const float* __restrict__ Wv1,
               const float* __restrict__ Wv2,const float* __restrict__ Wo)
{
    int idx = blockIdx.x * 256 + threadIdx.x;
    if (idx >= PREP_TOTAL) return;

    const float4* src;
    float4* dst;
    if (idx < 786432)        { src = (const float4*)x   + idx;           dst = (float4*)g_x    + idx; }
    else if (idx < 1081344)  { int i = idx - 786432;  src = (const float4*)Wq  + i; dst = (float4*)g_wqkv + i; }
    else if (idx < 1179648)  { int i = idx - 1081344; src = (const float4*)Wk  + i; dst = (float4*)g_wqkv + 294912 + i; }
    else if (idx < 1228800)  { int i = idx - 1179648; src = (const float4*)Wv1 + i; dst = (float4*)g_wqkv + 393216 + i; }
    else if (idx < 1277952)  { int i = idx - 1228800; src = (const float4*)Wv2 + i; dst = (float4*)g_wqkv + 442368 + i; }
    else                     { int i = idx - 1277952; src = (const float4*)Wo  + i; dst = (float4*)g_wo   + i; }

    float4 v = *src;
    v.x = to_tf32(v.x); v.y = to_tf32(v.y);
    v.z = to_tf32(v.z); v.w = to_tf32(v.w);
    *dst = v;
}

// ---------------------------------------------------------------------------
// TF32 tensor-core GEMM (pre-rounded inputs). 128x128 tile, cp.async 2-stage.
// ---------------------------------------------------------------------------
#define TBM 128
#define TBN 128
#define TBK 32
#define GPAD 36
#define GEMM_SMEM_BYTES (2 * 2 * TBM * GPAD * 4)   // 73728

__global__ __launch_bounds__(256, 2)
void gemm_tf32(const float* __restrict__ A, const float* __restrict__ W,
               const float* __restrict__ bias, float* __restrict__ C,
               int M, int N, int K, int round_col)
{
    extern __shared__ float sm[];
    float* As = sm;
    float* Ws = sm + 2 * TBM * GPAD;

    const int tid  = threadIdx.x;
    const int lane = tid & 31;
    const int warp = tid >> 5;
    const int wm   = (warp & 1) * 64;
    const int wn   = (warp >> 1) * 32;
    const int gid  = lane >> 2;
    const int tig  = lane & 3;

    const int m0 = blockIdx.y * TBM;
    const int n0 = blockIdx.x * TBN;
    const bool roundv = (n0 >= round_col);

    const int lr = tid >> 3;
    const int lc = (tid & 7) * 4;

    auto load_stage = [&](int st, int k0) {
#pragma unroll
        for (int i = 0; i < 4; i++) {
            int r = lr + 32 * i;
            cpa16(As + (st * TBM + r) * GPAD + lc, A + (size_t)(m0 + r) * K + k0 + lc);
            cpa16(Ws + (st * TBN + r) * GPAD + lc, W + (size_t)(n0 + r) * K + k0 + lc);
        }
        asm volatile("cp.async.commit_group;\n" ::: "memory");
    };

    float acc[4][4][4];
#pragma unroll
    for (int i = 0; i < 4; i++)
#pragma unroll
        for (int j = 0; j < 4; j++)
#pragma unroll
            for (int l = 0; l < 4; l++) acc[i][j][l] = 0.f;

    const int nkt = K / TBK;
    load_stage(0, 0);

    for (int kt = 0; kt < nkt; kt++) {
        const int cur = kt & 1;
        if (kt + 1 < nkt) {
            load_stage(cur ^ 1, (kt + 1) * TBK);
            asm volatile("cp.async.wait_group 1;\n" ::: "memory");
        } else {
            asm volatile("cp.async.wait_group 0;\n" ::: "memory");
        }
        __syncthreads();

        const float* Ab = As + cur * TBM * GPAD;
        const float* Wb = Ws + cur * TBN * GPAD;

#pragma unroll
        for (int ks = 0; ks < 4; ks++) {
            const int kk = ks * 8;
            uint32_t bfr[4][2];
#pragma unroll
            for (int nt = 0; nt < 4; nt++) {
                int n = wn + nt * 8 + gid;
                bfr[nt][0] = __float_as_uint(Wb[n * GPAD + kk + tig]);
                bfr[nt][1] = __float_as_uint(Wb[n * GPAD + kk + tig + 4]);
            }
#pragma unroll
            for (int mt = 0; mt < 4; mt++) {
                int m = wm + mt * 16 + gid;
                uint32_t af[4];
                af[0] = __float_as_uint(Ab[m * GPAD + kk + tig]);
                af[1] = __float_as_uint(Ab[(m + 8) * GPAD + kk + tig]);
                af[2] = __float_as_uint(Ab[m * GPAD + kk + tig + 4]);
                af[3] = __float_as_uint(Ab[(m + 8) * GPAD + kk + tig + 4]);
#pragma unroll
                for (int nt = 0; nt < 4; nt++)
                    mma_tf32(acc[mt][nt], af, bfr[nt]);
            }
        }
        __syncthreads();
    }

#pragma unroll
    for (int mt = 0; mt < 4; mt++) {
        int m = m0 + wm + mt * 16 + gid;
#pragma unroll
        for (int nt = 0; nt < 4; nt++) {
            int n = n0 + wn + nt * 8 + 2 * tig;
            float b0 = bias ? bias[n] : 0.f;
            float b1 = bias ? bias[n + 1] : 0.f;
            float2 r0 = make_float2(acc[mt][nt][0] + b0, acc[mt][nt][1] + b1);
            float2 r1 = make_float2(acc[mt][nt][2] + b0, acc[mt][nt][3] + b1);
            if (roundv) {
                r0.x = to_tf32(r0.x); r0.y = to_tf32(r0.y);
                r1.x = to_tf32(r1.x); r1.y = to_tf32(r1.y);
            }
            *reinterpret_cast<float2*>(C + (size_t)m * N + n) = r0;
            *reinterpret_cast<float2*>(C + (size_t)(m + 8) * N + n) = r1;
        }
    }
}

// ---------------------------------------------------------------------------
// 2D RoPE + qk-norm (one warp per 64-vector). tf32-rounded output.
// ---------------------------------------------------------------------------
__global__ __launch_bounds__(256)
void rope_norm(float* __restrict__ buf, int vpr, int stride, int total_vec)
{
    const int gw   = (blockIdx.x * blockDim.x + threadIdx.x) >> 5;
    const int lane = threadIdx.x & 31;
    if (gw >= total_vec) return;

    const int row = gw / vpr;
    const int vec = gw - row * vpr;
    const int n   = row & (N_ - 1);
    const float ph = (float)(n >> 5);
    const float pw = (float)(n & 31);

    float* p = buf + (size_t)row * stride + vec * 64;
    float x0 = p[lane];
    float x1 = p[lane + 32];

    float inv = exp2f((float)lane * -0.4152410118609203f);
    float t0 = ph * inv, t1 = pw * inv;
    float c0, s0, c1, s1;
    __sincosf(t0, &s0, &c0);
    __sincosf(t1, &s1, &c1);

    float px0 = __shfl_xor_sync(0xffffffffu, x0, 1);
    float px1 = __shfl_xor_sync(0xffffffffu, x1, 1);
    float r0 = (lane & 1) ? px0 : -px0;
    float r1 = (lane & 1) ? px1 : -px1;

    float o0 = x0 * c0 + r0 * s0;
    float o1 = x1 * c1 + r1 * s1;

    float ss = o0 * o0 + o1 * o1;
#pragma unroll
    for (int o = 16; o; o >>= 1) ss += __shfl_xor_sync(0xffffffffu, ss, o);
    float sc = 1.f / (sqrtf(ss) + 1e-6f);

    p[lane]      = to_tf32(o0 * sc);
    p[lane + 32] = to_tf32(o1 * sc);
}

// ---------------------------------------------------------------------------
// Tensor-core windowed attention, one side per block.
// Block = (b, kh, side, ph): 1024 blocks, 3 warps (96 thr). Warp = head.
// Round-11 changes vs round 10:
//   - polynomial exp (degree-4 Taylor, |x|<=0.125): no MUFU in hot loop
//   - dead S-tile elision: (mt=0,nt=3) and (mt=1,nt=0) are fully outside
//     the |pw-ck|<=8 band -> skip their S-MMAs + exp + stores; their sP
//     regions zeroed once before the loop.
// ---------------------------------------------------------------------------
#define KV_STRIDE_K 68
#define KV_STRIDE_V 72
#define KV_STAGE    (32 * KV_STRIDE_K + 32 * KV_STRIDE_V)   // 4480
#define ATT_SMEM_FLOATS (2 * KV_STAGE + 3456)
#define ATT_SMEM_BYTES  (ATT_SMEM_FLOATS * 4)

__device__ __forceinline__ bool dead_tile(int mt, int nt) {
    return (mt == 0 && nt == 3) || (mt == 1 && nt == 0);
}

__global__ __launch_bounds__(96, 4)
void attn_tc(const float* __restrict__ lambda_p)
{
    extern __shared__ float sm[];
    float* sKV = sm;                     // [2 stages][K 32x68 | V 32x72]
    float* sP  = sm + 2 * KV_STAGE;      // [3][32][36]

    const int tid  = threadIdx.x;
    const int lane = tid & 31;
    const int warp = tid >> 5;           // 0..2 = head-local
    const int gid  = lane >> 2;
    const int tig  = lane & 3;

    const int blk  = blockIdx.x;         // b(4) x kh(4) x side(2) x ph(32)
    const int ph   = blk & 31;
    const int side = (blk >> 5) & 1;
    const int kh   = (blk >> 6) & 3;
    const int b    = blk >> 8;

    const int hloc = warp;
    const int h    = kh * 3 + hloc;

    const int rlo = max(ph - WIN_, 0);
    const int rhi = min(ph + WIN_, SIDE_ - 1);
    const int nit = rhi - rlo + 1;

    const int colK = OFF_K  + side * 256 + kh * 64;
    const int colV = OFF_V1 + side * 256 + kh * 64;

    // precomputed column mask (live tiles only)
    uint32_t mbits = 0;
#pragma unroll
    for (int mt = 0; mt < 2; mt++)
#pragma unroll
        for (int nt = 0; nt < 4; nt++)
#pragma unroll
            for (int c = 0; c < 4; c++) {
                int pwq = mt * 16 + gid + ((c >> 1) << 3);
                int ck  = nt * 8 + 2 * tig + (c & 1);
                int d = pwq - ck; d = (d < 0) ? -d : d;
                if (d <= WIN_) mbits |= 1u << (mt * 16 + nt * 4 + c);
            }

    auto load_stage = [&](int st, int r) {
#pragma unroll
        for (int i = 0; i < 11; i++) {
            int idx = tid + i * 96;
            if (idx < 1024) {
                int arr = idx >> 9;           // 0 = K, 1 = V
                int key = (idx >> 4) & 31;
                int f4  = (idx & 15) * 4;
                int col = arr ? colV : colK;
                const float* src = g_proj + (size_t)(b * N_ + r * 32 + key) * PROJ_N
                                 + col + f4;
                float* dst = sKV + st * KV_STAGE
                           + (arr ? 32 * KV_STRIDE_K + key * KV_STRIDE_V
                                  : key * KV_STRIDE_K) + f4;
                cpa16(dst, src);
            }
        }
        asm volatile("cp.async.commit_group;\n" ::: "memory");
    };

    load_stage(0, rlo);

    // Q fragments (already tf32)
    uint32_t qf[2][8][4];
    {
        const float* qb = g_proj + ((size_t)(b * N_ + ph * 32)) * PROJ_N + side * 768 + h * 64;
#pragma unroll
        for (int mt = 0; mt < 2; mt++) {
            const float* q0 = qb + (size_t)(mt * 16 + gid) * PROJ_N;
            const float* q1 = q0 + (size_t)8 * PROJ_N;
#pragma unroll
            for (int kt = 0; kt < 8; kt++) {
                qf[mt][kt][0] = __float_as_uint(q0[kt * 8 + tig]);
                qf[mt][kt][1] = __float_as_uint(q1[kt * 8 + tig]);
                qf[mt][kt][2] = __float_as_uint(q0[kt * 8 + tig + 4]);
                qf[mt][kt][3] = __float_as_uint(q1[kt * 8 + tig + 4]);
            }
        }
    }

    float o[2][8][4];
#pragma unroll
    for (int mt = 0; mt < 2; mt++)
#pragma unroll
        for (int nt = 0; nt < 8; nt++)
#pragma unroll
            for (int c = 0; c < 4; c++) o[mt][nt][c] = 0.f;

    float l_[2][2] = {{0.f, 0.f}, {0.f, 0.f}};

    float* sPw = sP + warp * 1152;       // [32][36]

    // zero the permanently-dead P regions once:
    //   (mt0,nt3): rows gid, gid+8, cols 24..31
    //   (mt1,nt0): rows 16+gid, 24+gid, cols 0..7
    {
        int cc3 = 24 + 2 * tig, cc0 = 2 * tig;
        sPw[gid * 36 + cc3] = 0.f;        sPw[gid * 36 + cc3 + 1] = 0.f;
        sPw[(gid + 8) * 36 + cc3] = 0.f;  sPw[(gid + 8) * 36 + cc3 + 1] = 0.f;
        sPw[(16 + gid) * 36 + cc0] = 0.f; sPw[(16 + gid) * 36 + cc0 + 1] = 0.f;
        sPw[(24 + gid) * 36 + cc0] = 0.f; sPw[(24 + gid) * 36 + cc0 + 1] = 0.f;
    }

    asm volatile("cp.async.wait_group 0;\n" ::: "memory");
    __syncthreads();

    for (int it = 0; it < nit; it++) {
        const int cur = it & 1;
        if (it + 1 < nit) load_stage(cur ^ 1, rlo + it + 1);

        const float* K = sKV + cur * KV_STAGE;
        const float* V = K + 32 * KV_STRIDE_K;

        // ---- S = Q @ K^T (live tiles only: 6 of 8 per kt)
        float s[2][4][4];
#pragma unroll
        for (int mt = 0; mt < 2; mt++)
#pragma unroll
            for (int nt = 0; nt < 4; nt++)
#pragma unroll
                for (int c = 0; c < 4; c++) s[mt][nt][c] = 0.f;

#pragma unroll
        for (int kt = 0; kt < 8; kt++) {
            uint32_t bf[4][2];
#pragma unroll
            for (int nt = 0; nt < 4; nt++) {
                bf[nt][0] = __float_as_uint(K[(nt * 8 + gid) * KV_STRIDE_K + kt * 8 + tig]);
                bf[nt][1] = __float_as_uint(K[(nt * 8 + gid) * KV_STRIDE_K + kt * 8 + tig + 4]);
            }
#pragma unroll
            for (int mt = 0; mt < 2; mt++)
#pragma unroll
                for (int nt = 0; nt < 4; nt++) {
                    if (dead_tile(mt, nt)) continue;
                    mma_tf32(s[mt][nt], qf[mt][kt], bf[nt]);
                }
        }

        // ---- masked polynomial exp + P store + partial sums (live tiles)
        __syncwarp();
#pragma unroll
        for (int mt = 0; mt < 2; mt++)
#pragma unroll
            for (int nt = 0; nt < 4; nt++) {
                if (dead_tile(mt, nt)) continue;
                float p[4];
#pragma unroll
                for (int c = 0; c < 4; c++) {
                    float e = exp_small(s[mt][nt][c] * 0.125f);
                    p[c] = (mbits >> (mt * 16 + nt * 4 + c)) & 1 ? e : 0.f;
                }
                l_[mt][0] += p[0] + p[1];
                l_[mt][1] += p[2] + p[3];
                int r0 = mt * 16 + gid, r1 = r0 + 8, cc = nt * 8 + 2 * tig;
                sPw[r0 * 36 + cc]     = __uint_as_float(f2tf(p[0]));
                sPw[r0 * 36 + cc + 1] = __uint_as_float(f2tf(p[1]));
                sPw[r1 * 36 + cc]     = __uint_as_float(f2tf(p[2]));
                sPw[r1 * 36 + cc + 1] = __uint_as_float(f2tf(p[3]));
            }
        __syncwarp();

        // ---- O += P @ V  (32 x 64, k = 32)
#pragma unroll
        for (int kt = 0; kt < 4; kt++) {
            uint32_t af[2][4];
#pragma unroll
            for (int mt = 0; mt < 2; mt++) {
                int r0 = mt * 16 + gid;
                af[mt][0] = __float_as_uint(sPw[r0 * 36 + kt * 8 + tig]);
                af[mt][1] = __float_as_uint(sPw[(r0 + 8) * 36 + kt * 8 + tig]);
                af[mt][2] = __float_as_uint(sPw[r0 * 36 + kt * 8 + tig + 4]);
                af[mt][3] = __float_as_uint(sPw[(r0 + 8) * 36 + kt * 8 + tig + 4]);
            }
#pragma unroll
            for (int nt = 0; nt < 8; nt++) {
                uint32_t bf[2];
                bf[0] = __float_as_uint(V[(kt * 8 + tig) * KV_STRIDE_V + nt * 8 + gid]);
                bf[1] = __float_as_uint(V[(kt * 8 + tig + 4) * KV_STRIDE_V + nt * 8 + gid]);
                mma_tf32(o[0][nt], af[0], bf);
                mma_tf32(o[1][nt], af[1], bf);
            }
        }

        asm volatile("cp.async.wait_group 0;\n" ::: "memory");
        __syncthreads();
    }

    // ---- final row-sum reduction
#pragma unroll
    for (int mt = 0; mt < 2; mt++)
#pragma unroll
        for (int hf = 0; hf < 2; hf++) {
            float r = l_[mt][hf];
            r += __shfl_xor_sync(0xffffffffu, r, 1);
            r += __shfl_xor_sync(0xffffffffu, r, 2);
            l_[mt][hf] = r;
        }

    // side 0: write O/l; side 1: write softplus(lambda) * O/l
    float lam = side ? log1pf(__expf(lambda_p[h])) : 1.f;
    float inv[2][2] = {{lam / l_[0][0], lam / l_[0][1]},
                       {lam / l_[1][0], lam / l_[1][1]}};

    float* dst = g_od + ((size_t)side * M_ROWS + (size_t)(b * N_ + ph * 32)) * 768 + h * 64;
#pragma unroll
    for (int mt = 0; mt < 2; mt++)
#pragma unroll
        for (int nt = 0; nt < 8; nt++) {
            int r0 = mt * 16 + gid, r1 = r0 + 8, cc = nt * 8 + 2 * tig;
            float2 v0, v1;
            v0.x = o[mt][nt][0] * inv[mt][0];
            v0.y = o[mt][nt][1] * inv[mt][0];
            v1.x = o[mt][nt][2] * inv[mt][1];
            v1.y = o[mt][nt][3] * inv[mt][1];
            *reinterpret_cast<float2*>(dst + (size_t)r0 * 768 + cc) = v0;
            *reinterpret_cast<float2*>(dst + (size_t)r1 * 768 + cc) = v1;
        }
}

// ---------------------------------------------------------------------------
// Combine: ctx = tf32(O1 - O2_scaled), float4-wide.
// ---------------------------------------------------------------------------
#define CTX_F4 (M_ROWS * DIM_ / 4)   // 786432

__global__ __launch_bounds__(256)
void combine_o()
{
    int idx = blockIdx.x * 256 + threadIdx.x;
    if (idx >= CTX_F4) return;
    const float4* o1 = reinterpret_cast<const float4*>(g_od);
    const float4* o2 = reinterpret_cast<const float4*>(g_od + (size_t)M_ROWS * DIM_);
    float4 a = o1[idx], c = o2[idx];
    float4 r;
    r.x = to_tf32(a.x - c.x);
    r.y = to_tf32(a.y - c.y);
    r.z = to_tf32(a.z - c.z);
    r.w = to_tf32(a.w - c.w);
    reinterpret_cast<float4*>(g_ctx)[idx] = r;
}

// ---------------------------------------------------------------------------
// Launch
// ---------------------------------------------------------------------------
extern "C" void kernel_launch(void* const* d_in, const int* in_sizes, int n_in,
                              void* d_out, int out_size)
{
    const float* x      = (const float*)d_in[0];
    const float* Wq     = (const float*)d_in[1];
    const float* Wk     = (const float*)d_in[2];
    const float* Wv1    = (const float*)d_in[3];
    const float* Wv2    = (const float*)d_in[4];
    const float* lam_p  = (const float*)d_in[5];
    const float* Wo     = (const float*)d_in[6];
    const float* bo     = (const float*)d_in[7];
    float* out = (float*)d_out;

    float *gx, *gw, *gwo, *proj, *ctx;
    cudaGetSymbolAddress((void**)&gx,   g_x);
    cudaGetSymbolAddress((void**)&gw,   g_wqkv);
    cudaGetSymbolAddress((void**)&gwo,  g_wo);
    cudaGetSymbolAddress((void**)&proj, g_proj);
    cudaGetSymbolAddress((void**)&ctx,  g_ctx);

    cudaFuncSetAttribute(gemm_tf32, cudaFuncAttributeMaxDynamicSharedMemorySize,
                         GEMM_SMEM_BYTES);
    cudaFuncSetAttribute(attn_tc, cudaFuncAttributeMaxDynamicSharedMemorySize,
                         ATT_SMEM_BYTES);
    cudaFuncSetAttribute(attn_tc, cudaFuncAttributePreferredSharedMemoryCarveout,
                         100);

    // tf32 pre-rounding + weight concat
    prep_tf32<<<(PREP_TOTAL + 255) / 256, 256>>>(x, Wq, Wk, Wv1, Wv2, Wo);

    // fused projections: one GEMM [4096 x 2560 x 768]; v1/v2 columns rounded
    gemm_tf32<<<dim3(PROJ_N / TBN, M_ROWS / TBM), 256, GEMM_SMEM_BYTES>>>(
        gx, gw, nullptr, proj, M_ROWS, PROJ_N, DIM_, OFF_V1);

    // RoPE + qk-norm over q+k (tf32-rounded output)
    {
        int vec = M_ROWS * 32;
        rope_norm<<<(vec * 32 + 255) / 256, 256>>>(proj, 32, PROJ_N, vec);
    }

    // tensor-core windowed attention: one side per block, 1024 blocks
    attn_tc<<<B_ * KV_ * 2 * SIDE_, 96, ATT_SMEM_BYTES>>>(lam_p);

    // differential combine
    combine_o<<<(CTX_F4 + 255) / 256, 256>>>();

    // output projection + bias
    gemm_tf32<<<dim3(DIM_ / TBN, M_ROWS / TBM), 256, GEMM_SMEM_BYTES>>>(
        ctx, gwo, bo, out, M_ROWS, DIM_, DIM_, 1 << 30);
}

// round 12
// speedup vs baseline: 1.0032x; 1.0032x over previous
#include <cuda_runtime.h>
#include <math.h>
#include <stdint.h>

// Problem constants
#define B_    4
#define N_    1024
#define DIM_  768
#define H_    12
#define KV_   4
#define D_    64
#define SIDE_ 32
#define WIN_  8
#define REP_  (H_ / KV_)       // 3
#define M_ROWS (B_ * N_)       // 4096

// Fused projection layout: [row][2560] = q(0..1535) | k(1536..2047) | v1(2048..2303) | v2(2304..2559)
#define PROJ_N 2560
#define OFF_K  1536
#define OFF_V1 2048

// ---------------------------------------------------------------------------
// Scratch
// ---------------------------------------------------------------------------
__device__ float g_x   [M_ROWS * DIM_];
__device__ float g_wqkv[PROJ_N * DIM_];
__device__ float g_wo  [DIM_ * DIM_];
__device__ float g_proj[M_ROWS * PROJ_N];
__device__ float g_od  [2 * M_ROWS * DIM_];   // per-side normalized O
__device__ float g_ctx [M_ROWS * DIM_];

// ---------------------------------------------------------------------------
// PTX helpers
// ---------------------------------------------------------------------------
__device__ __forceinline__ float to_tf32(float x) {
    asm("cvt.rna.tf32.f32 %0, %0;" : "+f"(x));
    return x;
}
__device__ __forceinline__ uint32_t f2tf(float x) {
    asm("cvt.rna.tf32.f32 %0, %0;" : "+f"(x));
    return __float_as_uint(x);
}
__device__ __forceinline__ void mma_tf32(float* c, const uint32_t* a, const uint32_t* b) {
    asm volatile(
        "mma.sync.aligned.m16n8k8.row.col.f32.tf32.tf32.f32 "
        "{%0,%1,%2,%3}, {%4,%5,%6,%7}, {%8,%9}, {%0,%1,%2,%3};\n"
        : "+f"(c[0]), "+f"(c[1]), "+f"(c[2]), "+f"(c[3])
        : "r"(a[0]), "r"(a[1]), "r"(a[2]), "r"(a[3]), "r"(b[0]), "r"(b[1]));
}
__device__ __forceinline__ void cpa16(float* dst, const float* src) {
    unsigned u = (unsigned)__cvta_generic_to_shared(dst);
    asm volatile("cp.async.cg.shared.global [%0], [%1], 16;\n" :: "r"(u), "l"(src));
}
// exp(x) for |x| <= 0.125: degree-4 Taylor, max rel err ~2.5e-7, pure FMA.
__device__ __forceinline__ float exp_small(float x) {
    float r = fmaf(x, 0.041666667f, 0.16666667f);
    r = fmaf(x, r, 0.5f);
    r = fmaf(x, r, 1.0f);
    r = fmaf(x, r, 1.0f);
    return r;
}

// ---------------------------------------------------------------------------
// Prep: tf32-round x, concat+round weights (float4 per thread).
// ---------------------------------------------------------------------------
#define PREP_TOTAL 1425408

__global__ __launch_bounds__(256)
void prep_tf32(const float* __restrict__ x,  const float* __restrict__ Wq,
               const float* __restrict__ Wk, const float* __restrict__ Wv1,
               const float* __restrict__ Wv2,const float* __restrict__ Wo)
{
    int idx = blockIdx.x * 256 + threadIdx.x;
    if (idx >= PREP_TOTAL) return;

    const float4* src;
    float4* dst;
    if (idx < 786432)        { src = (const float4*)x   + idx;           dst = (float4*)g_x    + idx; }
    else if (idx < 1081344)  { int i = idx - 786432;  src = (const float4*)Wq  + i; dst = (float4*)g_wqkv + i; }
    else if (idx < 1179648)  { int i = idx - 1081344; src = (const float4*)Wk  + i; dst = (float4*)g_wqkv + 294912 + i; }
    else if (idx < 1228800)  { int i = idx - 1179648; src = (const float4*)Wv1 + i; dst = (float4*)g_wqkv + 393216 + i; }
    else if (idx < 1277952)  { int i = idx - 1228800; src = (const float4*)Wv2 + i; dst = (float4*)g_wqkv + 442368 + i; }
    else                     { int i = idx - 1277952; src = (const float4*)Wo  + i; dst = (float4*)g_wo   + i; }

    float4 v = *src;
    v.x = to_tf32(v.x); v.y = to_tf32(v.y);
    v.z = to_tf32(v.z); v.w = to_tf32(v.w);
    *dst = v;
}

// ---------------------------------------------------------------------------
// TF32 tensor-core GEMM (pre-rounded inputs). 128x128 tile, cp.async 2-stage.
// ---------------------------------------------------------------------------
#define TBM 128
#define TBN 128
#define TBK 32
#define GPAD 36
#define GEMM_SMEM_BYTES (2 * 2 * TBM * GPAD * 4)   // 73728

__global__ __launch_bounds__(256, 2)
void gemm_tf32(const float* __restrict__ A, const float* __restrict__ W,
               const float* __restrict__ bias, float* __restrict__ C,
               int M, int N, int K, int round_col)
{
    extern __shared__ float sm[];
    float* As = sm;
    float* Ws = sm + 2 * TBM * GPAD;

    const int tid  = threadIdx.x;
    const int lane = tid & 31;
    const int warp = tid >> 5;
    const int wm   = (warp & 1) * 64;
    const int wn   = (warp >> 1) * 32;
    const int gid  = lane >> 2;
    const int tig  = lane & 3;

    const int m0 = blockIdx.y * TBM;
    const int n0 = blockIdx.x * TBN;
    const bool roundv = (n0 >= round_col);

    const int lr = tid >> 3;
    const int lc = (tid & 7) * 4;

    auto load_stage = [&](int st, int k0) {
#pragma unroll
        for (int i = 0; i < 4; i++) {
            int r = lr + 32 * i;
            cpa16(As + (st * TBM + r) * GPAD + lc, A + (size_t)(m0 + r) * K + k0 + lc);
            cpa16(Ws + (st * TBN + r) * GPAD + lc, W + (size_t)(n0 + r) * K + k0 + lc);
        }
        asm volatile("cp.async.commit_group;\n" ::: "memory");
    };

    float acc[4][4][4];
#pragma unroll
    for (int i = 0; i < 4; i++)
#pragma unroll
        for (int j = 0; j < 4; j++)
#pragma unroll
            for (int l = 0; l < 4; l++) acc[i][j][l] = 0.f;

    const int nkt = K / TBK;
    load_stage(0, 0);

    for (int kt = 0; kt < nkt; kt++) {
        const int cur = kt & 1;
        if (kt + 1 < nkt) {
            load_stage(cur ^ 1, (kt + 1) * TBK);
            asm volatile("cp.async.wait_group 1;\n" ::: "memory");
        } else {
            asm volatile("cp.async.wait_group 0;\n" ::: "memory");
        }
        __syncthreads();

        const float* Ab = As + cur * TBM * GPAD;
        const float* Wb = Ws + cur * TBN * GPAD;

#pragma unroll
        for (int ks = 0; ks < 4; ks++) {
            const int kk = ks * 8;
            uint32_t bfr[4][2];
#pragma unroll
            for (int nt = 0; nt < 4; nt++) {
                int n = wn + nt * 8 + gid;
                bfr[nt][0] = __float_as_uint(Wb[n * GPAD + kk + tig]);
                bfr[nt][1] = __float_as_uint(Wb[n * GPAD + kk + tig + 4]);
            }
#pragma unroll
            for (int mt = 0; mt < 4; mt++) {
                int m = wm + mt * 16 + gid;
                uint32_t af[4];
                af[0] = __float_as_uint(Ab[m * GPAD + kk + tig]);
                af[1] = __float_as_uint(Ab[(m + 8) * GPAD + kk + tig]);
                af[2] = __float_as_uint(Ab[m * GPAD + kk + tig + 4]);
                af[3] = __float_as_uint(Ab[(m + 8) * GPAD + kk + tig + 4]);
#pragma unroll
                for (int nt = 0; nt < 4; nt++)
                    mma_tf32(acc[mt][nt], af, bfr[nt]);
            }
        }
        __syncthreads();
    }

#pragma unroll
    for (int mt = 0; mt < 4; mt++) {
        int m = m0 + wm + mt * 16 + gid;
#pragma unroll
        for (int nt = 0; nt < 4; nt++) {
            int n = n0 + wn + nt * 8 + 2 * tig;
            float b0 = bias ? bias[n] : 0.f;
            float b1 = bias ? bias[n + 1] : 0.f;
            float2 r0 = make_float2(acc[mt][nt][0] + b0, acc[mt][nt][1] + b1);
            float2 r1 = make_float2(acc[mt][nt][2] + b0, acc[mt][nt][3] + b1);
            if (roundv) {
                r0.x = to_tf32(r0.x); r0.y = to_tf32(r0.y);
                r1.x = to_tf32(r1.x); r1.y = to_tf32(r1.y);
            }
            *reinterpret_cast<float2*>(C + (size_t)m * N + n) = r0;
            *reinterpret_cast<float2*>(C + (size_t)(m + 8) * N + n) = r1;
        }
    }
}

// ---------------------------------------------------------------------------
// 2D RoPE + qk-norm (one warp per 64-vector). tf32-rounded output.
// ---------------------------------------------------------------------------
__global__ __launch_bounds__(256)
void rope_norm(float* __restrict__ buf, int vpr, int stride, int total_vec)
{
    const int gw   = (blockIdx.x * blockDim.x + threadIdx.x) >> 5;
    const int lane = threadIdx.x & 31;
    if (gw >= total_vec) return;

    const int row = gw / vpr;
    const int vec = gw - row * vpr;
    const int n   = row & (N_ - 1);
    const float ph = (float)(n >> 5);
    const float pw = (float)(n & 31);

    float* p = buf + (size_t)row * stride + vec * 64;
    float x0 = p[lane];
    float x1 = p[lane + 32];

    float inv = exp2f((float)lane * -0.4152410118609203f);
    float t0 = ph * inv, t1 = pw * inv;
    float c0, s0, c1, s1;
    __sincosf(t0, &s0, &c0);
    __sincosf(t1, &s1, &c1);

    float px0 = __shfl_xor_sync(0xffffffffu, x0, 1);
    float px1 = __shfl_xor_sync(0xffffffffu, x1, 1);
    float r0 = (lane & 1) ? px0 : -px0;
    float r1 = (lane & 1) ? px1 : -px1;

    float o0 = x0 * c0 + r0 * s0;
    float o1 = x1 * c1 + r1 * s1;

    float ss = o0 * o0 + o1 * o1;
#pragma unroll
    for (int o = 16; o; o >>= 1) ss += __shfl_xor_sync(0xffffffffu, ss, o);
    float sc = 1.f / (sqrtf(ss) + 1e-6f);

    p[lane]      = to_tf32(o0 * sc);
    p[lane + 32] = to_tf32(o1 * sc);
}

// ---------------------------------------------------------------------------
// Tensor-core windowed attention, one side per block.
// Block = (b, kh, side, ph): 1024 blocks, 3 warps (96 thr). Warp = head.
// Round-12 changes vs round 11:
//   - P smem round-trip ELIMINATED: S-fragment -> PV A-fragment via
//     register shuffles (FA2-style C->A permutation). No sP, no STS/LDS-P,
//     no per-iteration __syncwarp.
//   - dead A-fragments (mt0,kt3)/(mt1,kt0) now also skip their PV MMAs.
//   - smem/CTA drops to 35.8 KB -> 4 CTAs/SM.
// ---------------------------------------------------------------------------
#define KV_STRIDE_K 68
#define KV_STRIDE_V 72
#define KV_STAGE    (32 * KV_STRIDE_K + 32 * KV_STRIDE_V)   // 4480
#define ATT_SMEM_FLOATS (2 * KV_STAGE)
#define ATT_SMEM_BYTES  (ATT_SMEM_FLOATS * 4)               // 35840

__global__ __launch_bounds__(96, 4)
void attn_tc(const float* __restrict__ lambda_p)
{
    extern __shared__ float sm[];
    float* sKV = sm;                     // [2 stages][K 32x68 | V 32x72]

    const int tid  = threadIdx.x;
    const int lane = tid & 31;
    const int warp = tid >> 5;           // 0..2 = head-local
    const int gid  = lane >> 2;
    const int tig  = lane & 3;

    const int blk  = blockIdx.x;         // b(4) x kh(4) x side(2) x ph(32)
    const int ph   = blk & 31;
    const int side = (blk >> 5) & 1;
    const int kh   = (blk >> 6) & 3;
    const int b    = blk >> 8;

    const int hloc = warp;
    const int h    = kh * 3 + hloc;

    const int rlo = max(ph - WIN_, 0);
    const int rhi = min(ph + WIN_, SIDE_ - 1);
    const int nit = rhi - rlo + 1;

    const int colK = OFF_K  + side * 256 + kh * 64;
    const int colV = OFF_V1 + side * 256 + kh * 64;

    // precomputed column mask: bit (mt*16 + nt*4 + c) = |pwq - ck| <= WIN
    uint32_t mbits = 0;
#pragma unroll
    for (int mt = 0; mt < 2; mt++)
#pragma unroll
        for (int nt = 0; nt < 4; nt++)
#pragma unroll
            for (int c = 0; c < 4; c++) {
                int pwq = mt * 16 + gid + ((c >> 1) << 3);
                int ck  = nt * 8 + 2 * tig + (c & 1);
                int d = pwq - ck; d = (d < 0) ? -d : d;
                if (d <= WIN_) mbits |= 1u << (mt * 16 + nt * 4 + c);
            }

    // shuffle sources for C->A fragment conversion
    const int shsrc = gid * 4 + (tig >> 1);     // col tig owner
    const bool shodd = tig & 1;

    auto load_stage = [&](int st, int r) {
#pragma unroll
        for (int i = 0; i < 11; i++) {
            int idx = tid + i * 96;
            if (idx < 1024) {
                int arr = idx >> 9;           // 0 = K, 1 = V
                int key = (idx >> 4) & 31;
                int f4  = (idx & 15) * 4;
                int col = arr ? colV : colK;
                const float* src = g_proj + (size_t)(b * N_ + r * 32 + key) * PROJ_N
                                 + col + f4;
                float* dst = sKV + st * KV_STAGE
                           + (arr ? 32 * KV_STRIDE_K + key * KV_STRIDE_V
                                  : key * KV_STRIDE_K) + f4;
                cpa16(dst, src);
            }
        }
        asm volatile("cp.async.commit_group;\n" ::: "memory");
    };

    load_stage(0, rlo);

    // Q fragments (already tf32)
    uint32_t qf[2][8][4];
    {
        const float* qb = g_proj + ((size_t)(b * N_ + ph * 32)) * PROJ_N + side * 768 + h * 64;
#pragma unroll
        for (int mt = 0; mt < 2; mt++) {
            const float* q0 = qb + (size_t)(mt * 16 + gid) * PROJ_N;
            const float* q1 = q0 + (size_t)8 * PROJ_N;
#pragma unroll
            for (int kt = 0; kt < 8; kt++) {
                qf[mt][kt][0] = __float_as_uint(q0[kt * 8 + tig]);
                qf[mt][kt][1] = __float_as_uint(q1[kt * 8 + tig]);
                qf[mt][kt][2] = __float_as_uint(q0[kt * 8 + tig + 4]);
                qf[mt][kt][3] = __float_as_uint(q1[kt * 8 + tig + 4]);
            }
        }
    }

    float o[2][8][4];
#pragma unroll
    for (int mt = 0; mt < 2; mt++)
#pragma unroll
        for (int nt = 0; nt < 8; nt++)
#pragma unroll
            for (int c = 0; c < 4; c++) o[mt][nt][c] = 0.f;

    float l_[2][2] = {{0.f, 0.f}, {0.f, 0.f}};

    asm volatile("cp.async.wait_group 0;\n" ::: "memory");
    __syncthreads();

    for (int it = 0; it < nit; it++) {
        const int cur = it & 1;
        if (it + 1 < nit) load_stage(cur ^ 1, rlo + it + 1);

        const float* K = sKV + cur * KV_STAGE;
        const float* V = K + 32 * KV_STRIDE_K;

        // ---- S = Q @ K^T (live tiles: skip (mt0,nt3),(mt1,nt0))
        float s[2][4][4];
#pragma unroll
        for (int mt = 0; mt < 2; mt++)
#pragma unroll
            for (int nt = 0; nt < 4; nt++)
#pragma unroll
                for (int c = 0; c < 4; c++) s[mt][nt][c] = 0.f;

#pragma unroll
        for (int kt = 0; kt < 8; kt++) {
            uint32_t bf[4][2];
#pragma unroll
            for (int nt = 0; nt < 4; nt++) {
                bf[nt][0] = __float_as_uint(K[(nt * 8 + gid) * KV_STRIDE_K + kt * 8 + tig]);
                bf[nt][1] = __float_as_uint(K[(nt * 8 + gid) * KV_STRIDE_K + kt * 8 + tig + 4]);
            }
#pragma unroll
            for (int mt = 0; mt < 2; mt++)
#pragma unroll
                for (int nt = 0; nt < 4; nt++) {
                    if ((mt == 0 && nt == 3) || (mt == 1 && nt == 0)) continue;
                    mma_tf32(s[mt][nt], qf[mt][kt], bf[nt]);
                }
        }

        // ---- exp + mask, then C->A fragment conversion via shuffles
        // af[mt][kt][*] : A-fragment of P for k-chunk kt (kt == nt grouping)
        uint32_t af[2][4][4];
#pragma unroll
        for (int mt = 0; mt < 2; mt++)
#pragma unroll
            for (int nt = 0; nt < 4; nt++) {
                const bool dead = (mt == 0 && nt == 3) || (mt == 1 && nt == 0);
                float p0 = 0.f, p1 = 0.f, p2 = 0.f, p3 = 0.f;
                if (!dead) {
                    p0 = exp_small(s[mt][nt][0] * 0.125f);
                    p1 = exp_small(s[mt][nt][1] * 0.125f);
                    p2 = exp_small(s[mt][nt][2] * 0.125f);
                    p3 = exp_small(s[mt][nt][3] * 0.125f);
                    p0 = (mbits >> (mt * 16 + nt * 4 + 0)) & 1 ? p0 : 0.f;
                    p1 = (mbits >> (mt * 16 + nt * 4 + 1)) & 1 ? p1 : 0.f;
                    p2 = (mbits >> (mt * 16 + nt * 4 + 2)) & 1 ? p2 : 0.f;
                    p3 = (mbits >> (mt * 16 + nt * 4 + 3)) & 1 ? p3 : 0.f;
                    l_[mt][0] += p0 + p1;
                    l_[mt][1] += p2 + p3;
                    // a0 = P[gid][8nt+tig], a1 = P[gid+8][..], a2/a3 at col tig+4
                    float t0 = __shfl_sync(0xffffffffu, p0, shsrc);
                    float t1 = __shfl_sync(0xffffffffu, p1, shsrc);
                    float t2 = __shfl_sync(0xffffffffu, p2, shsrc);
                    float t3 = __shfl_sync(0xffffffffu, p3, shsrc);
                    float u0 = __shfl_sync(0xffffffffu, p0, shsrc + 2);
                    float u1 = __shfl_sync(0xffffffffu, p1, shsrc + 2);
                    float u2 = __shfl_sync(0xffffffffu, p2, shsrc + 2);
                    float u3 = __shfl_sync(0xffffffffu, p3, shsrc + 2);
                    af[mt][nt][0] = f2tf(shodd ? t1 : t0);
                    af[mt][nt][1] = f2tf(shodd ? t3 : t2);
                    af[mt][nt][2] = f2tf(shodd ? u1 : u0);
                    af[mt][nt][3] = f2tf(shodd ? u3 : u2);
                } else {
                    af[mt][nt][0] = 0; af[mt][nt][1] = 0;
                    af[mt][nt][2] = 0; af[mt][nt][3] = 0;
                }
            }

        // ---- O += P @ V (skip dead A-fragments: 48 MMAs instead of 64)
#pragma unroll
        for (int kt = 0; kt < 4; kt++) {
#pragma unroll
            for (int nt = 0; nt < 8; nt++) {
                uint32_t bf[2];
                bf[0] = __float_as_uint(V[(kt * 8 + tig) * KV_STRIDE_V + nt * 8 + gid]);
                bf[1] = __float_as_uint(V[(kt * 8 + tig + 4) * KV_STRIDE_V + nt * 8 + gid]);
                if (kt != 3) mma_tf32(o[0][nt], af[0][kt], bf);
                if (kt != 0) mma_tf32(o[1][nt], af[1][kt], bf);
            }
        }

        asm volatile("cp.async.wait_group 0;\n" ::: "memory");
        __syncthreads();
    }

    // ---- final row-sum reduction
#pragma unroll
    for (int mt = 0; mt < 2; mt++)
#pragma unroll
        for (int hf = 0; hf < 2; hf++) {
            float r = l_[mt][hf];
            r += __shfl_xor_sync(0xffffffffu, r, 1);
            r += __shfl_xor_sync(0xffffffffu, r, 2);
            l_[mt][hf] = r;
        }

    // side 0: write O/l; side 1: write softplus(lambda) * O/l
    float lam = side ? log1pf(__expf(lambda_p[h])) : 1.f;
    float inv[2][2] = {{lam / l_[0][0], lam / l_[0][1]},
                       {lam / l_[1][0], lam / l_[1][1]}};

    float* dst = g_od + ((size_t)side * M_ROWS + (size_t)(b * N_ + ph * 32)) * 768 + h * 64;
#pragma unroll
    for (int mt = 0; mt < 2; mt++)
#pragma unroll
        for (int nt = 0; nt < 8; nt++) {
            int r0 = mt * 16 + gid, r1 = r0 + 8, cc = nt * 8 + 2 * tig;
            float2 v0, v1;
            v0.x = o[mt][nt][0] * inv[mt][0];
            v0.y = o[mt][nt][1] * inv[mt][0];
            v1.x = o[mt][nt][2] * inv[mt][1];
            v1.y = o[mt][nt][3] * inv[mt][1];
            *reinterpret_cast<float2*>(dst + (size_t)r0 * 768 + cc) = v0;
            *reinterpret_cast<float2*>(dst + (size_t)r1 * 768 + cc) = v1;
        }
}

// ---------------------------------------------------------------------------
// Combine: ctx = tf32(O1 - O2_scaled), float4-wide.
// ---------------------------------------------------------------------------
#define CTX_F4 (M_ROWS * DIM_ / 4)   // 786432

__global__ __launch_bounds__(256)
void combine_o()
{
    int idx = blockIdx.x * 256 + threadIdx.x;
    if (idx >= CTX_F4) return;
    const float4* o1 = reinterpret_cast<const float4*>(g_od);
    const float4* o2 = reinterpret_cast<const float4*>(g_od + (size_t)M_ROWS * DIM_);
    float4 a = o1[idx], c = o2[idx];
    float4 r;
    r.x = to_tf32(a.x - c.x);
    r.y = to_tf32(a.y - c.y);
    r.z = to_tf32(a.z - c.z);
    r.w = to_tf32(a.w - c.w);
    reinterpret_cast<float4*>(g_ctx)[idx] = r;
}

// ---------------------------------------------------------------------------
// Launch
// ---------------------------------------------------------------------------
extern "C" void kernel_launch(void* const* d_in, const int* in_sizes, int n_in,
                              void* d_out, int out_size)
{
    const float* x      = (const float*)d_in[0];
    const float* Wq     = (const float*)d_in[1];
    const float* Wk     = (const float*)d_in[2];
    const float* Wv1    = (const float*)d_in[3];
    const float* Wv2    = (const float*)d_in[4];
    const float* lam_p  = (const float*)d_in[5];
    const float* Wo     = (const float*)d_in[6];
    const float* bo     = (const float*)d_in[7];
    float* out = (float*)d_out;

    float *gx, *gw, *gwo, *proj, *ctx;
    cudaGetSymbolAddress((void**)&gx,   g_x);
    cudaGetSymbolAddress((void**)&gw,   g_wqkv);
    cudaGetSymbolAddress((void**)&gwo,  g_wo);
    cudaGetSymbolAddress((void**)&proj, g_proj);
    cudaGetSymbolAddress((void**)&ctx,  g_ctx);

    cudaFuncSetAttribute(gemm_tf32, cudaFuncAttributeMaxDynamicSharedMemorySize,
                         GEMM_SMEM_BYTES);
    cudaFuncSetAttribute(attn_tc, cudaFuncAttributeMaxDynamicSharedMemorySize,
                         ATT_SMEM_BYTES);
    cudaFuncSetAttribute(attn_tc, cudaFuncAttributePreferredSharedMemoryCarveout,
                         100);

    // tf32 pre-rounding + weight concat
    prep_tf32<<<(PREP_TOTAL + 255) / 256, 256>>>(x, Wq, Wk, Wv1, Wv2, Wo);

    // fused projections: one GEMM [4096 x 2560 x 768]; v1/v2 columns rounded
    gemm_tf32<<<dim3(PROJ_N / TBN, M_ROWS / TBM), 256, GEMM_SMEM_BYTES>>>(
        gx, gw, nullptr, proj, M_ROWS, PROJ_N, DIM_, OFF_V1);

    // RoPE + qk-norm over q+k (tf32-rounded output)
    {
        int vec = M_ROWS * 32;
        rope_norm<<<(vec * 32 + 255) / 256, 256>>>(proj, 32, PROJ_N, vec);
    }

    // tensor-core windowed attention: one side per block, 1024 blocks
    attn_tc<<<B_ * KV_ * 2 * SIDE_, 96, ATT_SMEM_BYTES>>>(lam_p);

    // differential combine
    combine_o<<<(CTX_F4 + 255) / 256, 256>>>();

    // output projection + bias
    gemm_tf32<<<dim3(DIM_ / TBN, M_ROWS / TBM), 256, GEMM_SMEM_BYTES>>>(
        ctx, gwo, bo, out, M_ROWS, DIM_, DIM_, 1 << 30);
}

// round 13
// speedup vs baseline: 1.1852x; 1.1815x over previous
#include <cuda_runtime.h>
#include <cuda_fp16.h>
#include <math.h>
#include <stdint.h>

// Problem constants
#define B_    4
#define N_    1024
#define DIM_  768
#define H_    12
#define KV_   4
#define D_    64
#define SIDE_ 32
#define WIN_  8
#define M_ROWS (B_ * N_)       // 4096

// Fused projection layout: [row][2560] = q(0..1535) | k(1536..2047) | v1(2048..2303) | v2(2304..2559)
#define PROJ_N 2560
#define OFF_V1 2048

// ---------------------------------------------------------------------------
// Scratch
// ---------------------------------------------------------------------------
__device__ float  g_x   [M_ROWS * DIM_];
__device__ float  g_wqkv[PROJ_N * DIM_];
__device__ float  g_wo  [DIM_ * DIM_];
__device__ float  g_proj[M_ROWS * PROJ_N];
__device__ __half g_qkh [M_ROWS * 2048];          // fp16 roped q|k, 16 MB
__device__ __half g_vt  [32 * 64 * 1024];         // fp16 V transposed: [bks][d][key]
__device__ float  g_od  [2 * M_ROWS * DIM_];      // per-side normalized O
__device__ float  g_ctx [M_ROWS * DIM_];

// ---------------------------------------------------------------------------
// PTX helpers
// ---------------------------------------------------------------------------
__device__ __forceinline__ float to_tf32(float x) {
    asm("cvt.rna.tf32.f32 %0, %0;" : "+f"(x));
    return x;
}
__device__ __forceinline__ void mma_tf32(float* c, const uint32_t* a, const uint32_t* b) {
    asm volatile(
        "mma.sync.aligned.m16n8k8.row.col.f32.tf32.tf32.f32 "
        "{%0,%1,%2,%3}, {%4,%5,%6,%7}, {%8,%9}, {%0,%1,%2,%3};\n"
        : "+f"(c[0]), "+f"(c[1]), "+f"(c[2]), "+f"(c[3])
        : "r"(a[0]), "r"(a[1]), "r"(a[2]), "r"(a[3]), "r"(b[0]), "r"(b[1]));
}
__device__ __forceinline__ void mma_f16(float* c, const uint32_t* a, const uint32_t* b) {
    asm volatile(
        "mma.sync.aligned.m16n8k16.row.col.f32.f16.f16.f32 "
        "{%0,%1,%2,%3}, {%4,%5,%6,%7}, {%8,%9}, {%0,%1,%2,%3};\n"
        : "+f"(c[0]), "+f"(c[1]), "+f"(c[2]), "+f"(c[3])
        : "r"(a[0]), "r"(a[1]), "r"(a[2]), "r"(a[3]), "r"(b[0]), "r"(b[1]));
}
__device__ __forceinline__ void cpa16(void* dst, const void* src) {
    unsigned u = (unsigned)__cvta_generic_to_shared(dst);
    asm volatile("cp.async.cg.shared.global [%0], [%1], 16;\n" :: "r"(u), "l"(src));
}
// pack 2 floats to half2 (x -> low, y -> high)
__device__ __forceinline__ uint32_t h2pack(float x, float y) {
    uint32_t r;
    asm("cvt.rn.f16x2.f32 %0, %1, %2;" : "=r"(r) : "f"(y), "f"(x));
    return r;
}
// exp(x) for |x| <= 0.125: degree-4 Taylor, max rel err ~2.5e-7.
__device__ __forceinline__ float exp_small(float x) {
    float r = fmaf(x, 0.041666667f, 0.16666667f);
    r = fmaf(x, r, 0.5f);
    r = fmaf(x, r, 1.0f);
    r = fmaf(x, r, 1.0f);
    return r;
}

// ---------------------------------------------------------------------------
// Prep: tf32-round x, concat+round weights (float4 per thread).
// ---------------------------------------------------------------------------
#define PREP_TOTAL 1425408

__global__ __launch_bounds__(256)
void prep_tf32(const float* __restrict__ x,  const float* __restrict__ Wq,
               const float* __restrict__ Wk, const float* __restrict__ Wv1,
               const float* __restrict__ Wv2,const float* __restrict__ Wo)
{
    int idx = blockIdx.x * 256 + threadIdx.x;
    if (idx >= PREP_TOTAL) return;

    const float4* src;
    float4* dst;
    if (idx < 786432)        { src = (const float4*)x   + idx;           dst = (float4*)g_x    + idx; }
    else if (idx < 1081344)  { int i = idx - 786432;  src = (const float4*)Wq  + i; dst = (float4*)g_wqkv + i; }
    else if (idx < 1179648)  { int i = idx - 1081344; src = (const float4*)Wk  + i; dst = (float4*)g_wqkv + 294912 + i; }
    else if (idx < 1228800)  { int i = idx - 1179648; src = (const float4*)Wv1 + i; dst = (float4*)g_wqkv + 393216 + i; }
    else if (idx < 1277952)  { int i = idx - 1228800; src = (const float4*)Wv2 + i; dst = (float4*)g_wqkv + 442368 + i; }
    else                     { int i = idx - 1277952; src = (const float4*)Wo  + i; dst = (float4*)g_wo   + i; }

    float4 v = *src;
    v.x = to_tf32(v.x); v.y = to_tf32(v.y);
    v.z = to_tf32(v.z); v.w = to_tf32(v.w);
    *dst = v;
}

// ---------------------------------------------------------------------------
// TF32 tensor-core GEMM (pre-rounded inputs). 128x128 tile, cp.async 2-stage.
// ---------------------------------------------------------------------------
#define TBM 128
#define TBN 128
#define TBK 32
#define GPAD 36
#define GEMM_SMEM_BYTES (2 * 2 * TBM * GPAD * 4)   // 73728

__global__ __launch_bounds__(256, 2)
void gemm_tf32(const float* __restrict__ A, const float* __restrict__ W,
               const float* __restrict__ bias, float* __restrict__ C,
               int M, int N, int K, int round_col)
{
    extern __shared__ float sm[];
    float* As = sm;
    float* Ws = sm + 2 * TBM * GPAD;

    const int tid  = threadIdx.x;
    const int lane = tid & 31;
    const int warp = tid >> 5;
    const int wm   = (warp & 1) * 64;
    const int wn   = (warp >> 1) * 32;
    const int gid  = lane >> 2;
    const int tig  = lane & 3;

    const int m0 = blockIdx.y * TBM;
    const int n0 = blockIdx.x * TBN;
    const bool roundv = (n0 >= round_col);

    const int lr = tid >> 3;
    const int lc = (tid & 7) * 4;

    auto load_stage = [&](int st, int k0) {
#pragma unroll
        for (int i = 0; i < 4; i++) {
            int r = lr + 32 * i;
            cpa16(As + (st * TBM + r) * GPAD + lc, A + (size_t)(m0 + r) * K + k0 + lc);
            cpa16(Ws + (st * TBN + r) * GPAD + lc, W + (size_t)(n0 + r) * K + k0 + lc);
        }
        asm volatile("cp.async.commit_group;\n" ::: "memory");
    };

    float acc[4][4][4];
#pragma unroll
    for (int i = 0; i < 4; i++)
#pragma unroll
        for (int j = 0; j < 4; j++)
#pragma unroll
            for (int l = 0; l < 4; l++) acc[i][j][l] = 0.f;

    const int nkt = K / TBK;
    load_stage(0, 0);

    for (int kt = 0; kt < nkt; kt++) {
        const int cur = kt & 1;
        if (kt + 1 < nkt) {
            load_stage(cur ^ 1, (kt + 1) * TBK);
            asm volatile("cp.async.wait_group 1;\n" ::: "memory");
        } else {
            asm volatile("cp.async.wait_group 0;\n" ::: "memory");
        }
        __syncthreads();

        const float* Ab = As + cur * TBM * GPAD;
        const float* Wb = Ws + cur * TBN * GPAD;

#pragma unroll
        for (int ks = 0; ks < 4; ks++) {
            const int kk = ks * 8;
            uint32_t bfr[4][2];
#pragma unroll
            for (int nt = 0; nt < 4; nt++) {
                int n = wn + nt * 8 + gid;
                bfr[nt][0] = __float_as_uint(Wb[n * GPAD + kk + tig]);
                bfr[nt][1] = __float_as_uint(Wb[n * GPAD + kk + tig + 4]);
            }
#pragma unroll
            for (int mt = 0; mt < 4; mt++) {
                int m = wm + mt * 16 + gid;
                uint32_t af[4];
                af[0] = __float_as_uint(Ab[m * GPAD + kk + tig]);
                af[1] = __float_as_uint(Ab[(m + 8) * GPAD + kk + tig]);
                af[2] = __float_as_uint(Ab[m * GPAD + kk + tig + 4]);
                af[3] = __float_as_uint(Ab[(m + 8) * GPAD + kk + tig + 4]);
#pragma unroll
                for (int nt = 0; nt < 4; nt++)
                    mma_tf32(acc[mt][nt], af, bfr[nt]);
            }
        }
        __syncthreads();
    }

#pragma unroll
    for (int mt = 0; mt < 4; mt++) {
        int m = m0 + wm + mt * 16 + gid;
#pragma unroll
        for (int nt = 0; nt < 4; nt++) {
            int n = n0 + wn + nt * 8 + 2 * tig;
            float b0 = bias ? bias[n] : 0.f;
            float b1 = bias ? bias[n + 1] : 0.f;
            float2 r0 = make_float2(acc[mt][nt][0] + b0, acc[mt][nt][1] + b1);
            float2 r1 = make_float2(acc[mt][nt][2] + b0, acc[mt][nt][3] + b1);
            if (roundv) {
                r0.x = to_tf32(r0.x); r0.y = to_tf32(r0.y);
                r1.x = to_tf32(r1.x); r1.y = to_tf32(r1.y);
            }
            *reinterpret_cast<float2*>(C + (size_t)m * N + n) = r0;
            *reinterpret_cast<float2*>(C + (size_t)(m + 8) * N + n) = r1;
        }
    }
}

// ---------------------------------------------------------------------------
// 2D RoPE + qk-norm. Reads g_proj fp32 q|k (cols 0..2047), writes fp16 g_qkh.
// ---------------------------------------------------------------------------
__global__ __launch_bounds__(256)
void rope_norm(int total_vec)
{
    const int gw   = (blockIdx.x * blockDim.x + threadIdx.x) >> 5;
    const int lane = threadIdx.x & 31;
    if (gw >= total_vec) return;

    const int row = gw >> 5;           // 32 vectors per row
    const int vec = gw & 31;
    const int n   = row & (N_ - 1);
    const float ph = (float)(n >> 5);
    const float pw = (float)(n & 31);

    const float* p = g_proj + (size_t)row * PROJ_N + vec * 64;
    float x0 = p[lane];
    float x1 = p[lane + 32];

    float inv = exp2f((float)lane * -0.4152410118609203f);
    float t0 = ph * inv, t1 = pw * inv;
    float c0, s0, c1, s1;
    __sincosf(t0, &s0, &c0);
    __sincosf(t1, &s1, &c1);

    float px0 = __shfl_xor_sync(0xffffffffu, x0, 1);
    float px1 = __shfl_xor_sync(0xffffffffu, x1, 1);
    float r0 = (lane & 1) ? px0 : -px0;
    float r1 = (lane & 1) ? px1 : -px1;

    float o0 = x0 * c0 + r0 * s0;
    float o1 = x1 * c1 + r1 * s1;

    float ss = o0 * o0 + o1 * o1;
#pragma unroll
    for (int o = 16; o; o >>= 1) ss += __shfl_xor_sync(0xffffffffu, ss, o);
    float sc = 1.f / (sqrtf(ss) + 1e-6f);

    __half* q = g_qkh + (size_t)row * 2048 + vec * 64;
    q[lane]      = __float2half_rn(o0 * sc);
    q[lane + 32] = __float2half_rn(o1 * sc);
}

// ---------------------------------------------------------------------------
// V transpose + fp16 convert: g_proj v cols -> g_vt[bks][d(64)][key(1024)].
// bks = (b*4+kh)*2+side. Grid: 1024 blocks (bks 0..31 x keyblk 0..31), 256 thr.
// ---------------------------------------------------------------------------
__global__ __launch_bounds__(256)
void v_transpose()
{
    __shared__ float tile[32][65];

    const int bks    = blockIdx.x >> 5;
    const int keyblk = blockIdx.x & 31;
    const int b    = bks >> 3;
    const int kh   = (bks >> 1) & 3;
    const int side = bks & 1;
    const int col0 = OFF_V1 + side * 256 + kh * 64;
    const int tid  = threadIdx.x;

    // load 32 keys x 64 d
    {
        int key = tid >> 3, seg = tid & 7;
        const float* src = g_proj + (size_t)(b * N_ + keyblk * 32 + key) * PROJ_N + col0 + seg * 8;
        float4 l0 = *reinterpret_cast<const float4*>(src);
        float4 l1 = *reinterpret_cast<const float4*>(src + 4);
        tile[key][seg * 8 + 0] = l0.x; tile[key][seg * 8 + 1] = l0.y;
        tile[key][seg * 8 + 2] = l0.z; tile[key][seg * 8 + 3] = l0.w;
        tile[key][seg * 8 + 4] = l1.x; tile[key][seg * 8 + 5] = l1.y;
        tile[key][seg * 8 + 6] = l1.z; tile[key][seg * 8 + 7] = l1.w;
    }
    __syncthreads();

    // write transposed fp16: 8 keys per thread, contiguous 16B
    {
        int d = tid >> 2, kq = tid & 3;
        uint32_t w[4];
#pragma unroll
        for (int j = 0; j < 4; j++)
            w[j] = h2pack(tile[kq * 8 + 2 * j][d], tile[kq * 8 + 2 * j + 1][d]);
        __half* dst = g_vt + (size_t)bks * 65536 + d * 1024 + keyblk * 32 + kq * 8;
        *reinterpret_cast<uint4*>(dst) = make_uint4(w[0], w[1], w[2], w[3]);
    }
}

// ---------------------------------------------------------------------------
// fp16 tensor-core windowed attention, one side per block.
// Block = (b, kh, side, ph): 1024 blocks, 3 warps (96 thr). Warp = head.
// m16n8k16 fp16 MMAs; K fp16 row-major, V fp16 d-major in smem.
// S C-frag -> PV A-frag is SHUFFLE-FREE (pack pairs to half2).
// smem/stage: K 32x72 halves (4608B) + Vt 64x40 halves (5120B) = 9728B; x2.
// ---------------------------------------------------------------------------
#define KST 72            // K smem row stride (halves)
#define VST 40            // Vt smem row stride (halves)
#define H_STAGE (32 * KST + 64 * VST)      // 4864 halves
#define ATT_SMEM_BYTES (2 * H_STAGE * 2)   // 19456

__global__ __launch_bounds__(96, 3)
void attn_tc(const float* __restrict__ lambda_p)
{
    extern __shared__ __half smh[];

    const int tid  = threadIdx.x;
    const int lane = tid & 31;
    const int warp = tid >> 5;           // 0..2 = head-local
    const int gid  = lane >> 2;
    const int tig  = lane & 3;

    const int blk  = blockIdx.x;         // b(4) x kh(4) x side(2) x ph(32)
    const int ph   = blk & 31;
    const int side = (blk >> 5) & 1;
    const int kh   = (blk >> 6) & 3;
    const int b    = blk >> 8;
    const int bks  = ((b * 4 + kh) * 2 + side);

    const int h = kh * 3 + warp;

    const int rlo = max(ph - WIN_, 0);
    const int rhi = min(ph + WIN_, SIDE_ - 1);
    const int nit = rhi - rlo + 1;

    const int kcol = 1536 + side * 256 + kh * 64;   // k cols in g_qkh

    // column mask: bit (mt*16 + nt*4 + c) = |pwq - ck| <= WIN
    uint32_t mbits = 0;
#pragma unroll
    for (int mt = 0; mt < 2; mt++)
#pragma unroll
        for (int nt = 0; nt < 4; nt++)
#pragma unroll
            for (int c = 0; c < 4; c++) {
                int pwq = mt * 16 + gid + ((c >> 1) << 3);
                int ck  = nt * 8 + 2 * tig + (c & 1);
                int d = pwq - ck; d = (d < 0) ? -d : d;
                if (d <= WIN_) mbits |= 1u << (mt * 16 + nt * 4 + c);
            }

    // loader: K 256 chunks + Vt 256 chunks of 16B, over 96 threads
    auto load_stage = [&](int st, int r) {
#pragma unroll
        for (int i = 0; i < 6; i++) {
            int idx = tid + i * 96;
            if (idx < 256) {
                int key = idx >> 3, j = idx & 7;
                const __half* src = g_qkh + (size_t)(b * N_ + r * 32 + key) * 2048 + kcol + j * 8;
                cpa16(smh + st * H_STAGE + key * KST + j * 8, src);
            } else if (idx < 512) {
                int i2 = idx - 256;
                int d = i2 >> 2, j = i2 & 3;
                const __half* src = g_vt + (size_t)bks * 65536 + d * 1024 + r * 32 + j * 8;
                cpa16(smh + st * H_STAGE + 32 * KST + d * VST + j * 8, src);
            }
        }
        asm volatile("cp.async.commit_group;\n" ::: "memory");
    };

    load_stage(0, rlo);

    // Q A-fragments (fp16): qf[mt][ktc][4], ktc = k16 chunk 0..3
    uint32_t qf[2][4][4];
    {
        const __half* qb = g_qkh + (size_t)(b * N_ + ph * 32) * 2048 + side * 768 + h * 64;
#pragma unroll
        for (int mt = 0; mt < 2; mt++) {
            const __half* q0 = qb + (size_t)(mt * 16 + gid) * 2048;
            const __half* q1 = q0 + (size_t)8 * 2048;
#pragma unroll
            for (int ktc = 0; ktc < 4; ktc++) {
                qf[mt][ktc][0] = *reinterpret_cast<const uint32_t*>(q0 + ktc * 16 + 2 * tig);
                qf[mt][ktc][1] = *reinterpret_cast<const uint32_t*>(q1 + ktc * 16 + 2 * tig);
                qf[mt][ktc][2] = *reinterpret_cast<const uint32_t*>(q0 + ktc * 16 + 8 + 2 * tig);
                qf[mt][ktc][3] = *reinterpret_cast<const uint32_t*>(q1 + ktc * 16 + 8 + 2 * tig);
            }
        }
    }

    float o[2][8][4];
#pragma unroll
    for (int mt = 0; mt < 2; mt++)
#pragma unroll
        for (int nt = 0; nt < 8; nt++)
#pragma unroll
            for (int c = 0; c < 4; c++) o[mt][nt][c] = 0.f;

    float l_[2][2] = {{0.f, 0.f}, {0.f, 0.f}};

    asm volatile("cp.async.wait_group 0;\n" ::: "memory");
    __syncthreads();

    for (int it = 0; it < nit; it++) {
        const int cur = it & 1;
        if (it + 1 < nit) load_stage(cur ^ 1, rlo + it + 1);

        const __half* K = smh + cur * H_STAGE;
        const __half* V = K + 32 * KST;

        // ---- S = Q @ K^T  (32x32, 4 k16 chunks; skip dead (0,3),(1,0))
        float s[2][4][4];
#pragma unroll
        for (int mt = 0; mt < 2; mt++)
#pragma unroll
            for (int nt = 0; nt < 4; nt++)
#pragma unroll
                for (int c = 0; c < 4; c++) s[mt][nt][c] = 0.f;

#pragma unroll
        for (int ktc = 0; ktc < 4; ktc++) {
            uint32_t bf[4][2];
#pragma unroll
            for (int nt = 0; nt < 4; nt++) {
                const __half* kr = K + (nt * 8 + gid) * KST + ktc * 16 + 2 * tig;
                bf[nt][0] = *reinterpret_cast<const uint32_t*>(kr);
                bf[nt][1] = *reinterpret_cast<const uint32_t*>(kr + 8);
            }
#pragma unroll
            for (int mt = 0; mt < 2; mt++)
#pragma unroll
                for (int nt = 0; nt < 4; nt++) {
                    if ((mt == 0 && nt == 3) || (mt == 1 && nt == 0)) continue;
                    mma_f16(s[mt][nt], qf[mt][ktc], bf[nt]);
                }
        }

        // ---- exp + mask + pack to fp16 A-fragments (shuffle-free)
        uint32_t paf[2][2][4];
#pragma unroll
        for (int mt = 0; mt < 2; mt++)
#pragma unroll
            for (int k2 = 0; k2 < 2; k2++)
#pragma unroll
                for (int q = 0; q < 4; q++) paf[mt][k2][q] = 0;

#pragma unroll
        for (int mt = 0; mt < 2; mt++)
#pragma unroll
            for (int nt = 0; nt < 4; nt++) {
                if ((mt == 0 && nt == 3) || (mt == 1 && nt == 0)) continue;
                float p0 = exp_small(s[mt][nt][0] * 0.125f);
                float p1 = exp_small(s[mt][nt][1] * 0.125f);
                float p2 = exp_small(s[mt][nt][2] * 0.125f);
                float p3 = exp_small(s[mt][nt][3] * 0.125f);
                p0 = (mbits >> (mt * 16 + nt * 4 + 0)) & 1 ? p0 : 0.f;
                p1 = (mbits >> (mt * 16 + nt * 4 + 1)) & 1 ? p1 : 0.f;
                p2 = (mbits >> (mt * 16 + nt * 4 + 2)) & 1 ? p2 : 0.f;
                p3 = (mbits >> (mt * 16 + nt * 4 + 3)) & 1 ? p3 : 0.f;
                l_[mt][0] += p0 + p1;
                l_[mt][1] += p2 + p3;
                paf[mt][nt >> 1][(nt & 1) * 2 + 0] = h2pack(p0, p1);  // row gid
                paf[mt][nt >> 1][(nt & 1) * 2 + 1] = h2pack(p2, p3);  // row gid+8
            }

        // ---- O += P @ V  (32x64, 2 k16 chunks over 32 keys)
#pragma unroll
        for (int k2 = 0; k2 < 2; k2++) {
#pragma unroll
            for (int nt = 0; nt < 8; nt++) {
                const __half* vr = V + (nt * 8 + gid) * VST + k2 * 16 + 2 * tig;
                uint32_t bf[2];
                bf[0] = *reinterpret_cast<const uint32_t*>(vr);
                bf[1] = *reinterpret_cast<const uint32_t*>(vr + 8);
                mma_f16(o[0][nt], paf[0][k2], bf);
                mma_f16(o[1][nt], paf[1][k2], bf);
            }
        }

        asm volatile("cp.async.wait_group 0;\n" ::: "memory");
        __syncthreads();
    }

    // ---- final row-sum reduction
#pragma unroll
    for (int mt = 0; mt < 2; mt++)
#pragma unroll
        for (int hf = 0; hf < 2; hf++) {
            float r = l_[mt][hf];
            r += __shfl_xor_sync(0xffffffffu, r, 1);
            r += __shfl_xor_sync(0xffffffffu, r, 2);
            l_[mt][hf] = r;
        }

    float lam = side ? log1pf(__expf(lambda_p[h])) : 1.f;
    float inv[2][2] = {{lam / l_[0][0], lam / l_[0][1]},
                       {lam / l_[1][0], lam / l_[1][1]}};

    float* dst = g_od + ((size_t)side * M_ROWS + (size_t)(b * N_ + ph * 32)) * 768 + h * 64;
#pragma unroll
    for (int mt = 0; mt < 2; mt++)
#pragma unroll
        for (int nt = 0; nt < 8; nt++) {
            int r0 = mt * 16 + gid, r1 = r0 + 8, cc = nt * 8 + 2 * tig;
            float2 v0, v1;
            v0.x = o[mt][nt][0] * inv[mt][0];
            v0.y = o[mt][nt][1] * inv[mt][0];
            v1.x = o[mt][nt][2] * inv[mt][1];
            v1.y = o[mt][nt][3] * inv[mt][1];
            *reinterpret_cast<float2*>(dst + (size_t)r0 * 768 + cc) = v0;
            *reinterpret_cast<float2*>(dst + (size_t)r1 * 768 + cc) = v1;
        }
}

// ---------------------------------------------------------------------------
// Combine: ctx = tf32(O1 - O2_scaled), float4-wide.
// ---------------------------------------------------------------------------
#define CTX_F4 (M_ROWS * DIM_ / 4)   // 786432

__global__ __launch_bounds__(256)
void combine_o()
{
    int idx = blockIdx.x * 256 + threadIdx.x;
    if (idx >= CTX_F4) return;
    const float4* o1 = reinterpret_cast<const float4*>(g_od);
    const float4* o2 = reinterpret_cast<const float4*>(g_od + (size_t)M_ROWS * DIM_);
    float4 a = o1[idx], c = o2[idx];
    float4 r;
    r.x = to_tf32(a.x - c.x);
    r.y = to_tf32(a.y - c.y);
    r.z = to_tf32(a.z - c.z);
    r.w = to_tf32(a.w - c.w);
    reinterpret_cast<float4*>(g_ctx)[idx] = r;
}

// ---------------------------------------------------------------------------
// Launch
// ---------------------------------------------------------------------------
extern "C" void kernel_launch(void* const* d_in, const int* in_sizes, int n_in,
                              void* d_out, int out_size)
{
    const float* x      = (const float*)d_in[0];
    const float* Wq     = (const float*)d_in[1];
    const float* Wk     = (const float*)d_in[2];
    const float* Wv1    = (const float*)d_in[3];
    const float* Wv2    = (const float*)d_in[4];
    const float* lam_p  = (const float*)d_in[5];
    const float* Wo     = (const float*)d_in[6];
    const float* bo     = (const float*)d_in[7];
    float* out = (float*)d_out;

    float *gx, *gw, *gwo, *proj, *ctx;
    cudaGetSymbolAddress((void**)&gx,   g_x);
    cudaGetSymbolAddress((void**)&gw,   g_wqkv);
    cudaGetSymbolAddress((void**)&gwo,  g_wo);
    cudaGetSymbolAddress((void**)&proj, g_proj);
    cudaGetSymbolAddress((void**)&ctx,  g_ctx);

    cudaFuncSetAttribute(gemm_tf32, cudaFuncAttributeMaxDynamicSharedMemorySize,
                         GEMM_SMEM_BYTES);
    cudaFuncSetAttribute(attn_tc, cudaFuncAttributeMaxDynamicSharedMemorySize,
                         ATT_SMEM_BYTES);

    // tf32 pre-rounding + weight concat
    prep_tf32<<<(PREP_TOTAL + 255) / 256, 256>>>(x, Wq, Wk, Wv1, Wv2, Wo);

    // fused projections: one GEMM [4096 x 2560 x 768] (no epilogue rounding)
    gemm_tf32<<<dim3(PROJ_N / TBN, M_ROWS / TBM), 256, GEMM_SMEM_BYTES>>>(
        gx, gw, nullptr, proj, M_ROWS, PROJ_N, DIM_, 1 << 30);

    // RoPE + qk-norm -> fp16 g_qkh
    {
        int vec = M_ROWS * 32;
        rope_norm<<<(vec * 32 + 255) / 256, 256>>>(vec);
    }

    // V transpose + fp16 convert -> g_vt
    v_transpose<<<1024, 256>>>();

    // fp16 tensor-core windowed attention
    attn_tc<<<B_ * KV_ * 2 * SIDE_, 96, ATT_SMEM_BYTES>>>(lam_p);

    // differential combine
    combine_o<<<(CTX_F4 + 255) / 256, 256>>>();

    // output projection + bias
    gemm_tf32<<<dim3(DIM_ / TBN, M_ROWS / TBM), 256, GEMM_SMEM_BYTES>>>(
        ctx, gwo, bo, out, M_ROWS, DIM_, DIM_, 1 << 30);
}

// round 14
// speedup vs baseline: 1.7379x; 1.4663x over previous
#include <cuda_runtime.h>
#include <cuda_fp16.h>
#include <math.h>
#include <stdint.h>

// Problem constants
#define B_    4
#define N_    1024
#define DIM_  768
#define H_    12
#define KV_   4
#define D_    64
#define SIDE_ 32
#define WIN_  8
#define M_ROWS (B_ * N_)       // 4096

// Fused projection layout: [row][2560] = q(0..1535) | k(1536..2047) | v1(2048..2303) | v2(2304..2559)
#define PROJ_N 2560
#define OFF_V1 2048

// ---------------------------------------------------------------------------
// Scratch
// ---------------------------------------------------------------------------
__device__ __half g_xh  [M_ROWS * DIM_];          // fp16 x
__device__ __half g_wh  [PROJ_N * DIM_];          // fp16 Wq|Wk|Wv1|Wv2
__device__ __half g_woh [DIM_ * DIM_];            // fp16 Wo
__device__ float  g_proj[M_ROWS * PROJ_N];        // fp32 projections
__device__ __half g_qkh [M_ROWS * 2048];          // fp16 roped q|k
__device__ __half g_vt  [32 * 64 * 1024];         // fp16 V transposed: [bks][d][key]
__device__ float  g_od  [2 * M_ROWS * DIM_];      // per-side normalized O
__device__ __half g_ctxh[M_ROWS * DIM_];          // fp16 ctx (Wo GEMM input)

// ---------------------------------------------------------------------------
// PTX helpers
// ---------------------------------------------------------------------------
__device__ __forceinline__ void mma_f16(float* c, const uint32_t* a, const uint32_t* b) {
    asm volatile(
        "mma.sync.aligned.m16n8k16.row.col.f32.f16.f16.f32 "
        "{%0,%1,%2,%3}, {%4,%5,%6,%7}, {%8,%9}, {%0,%1,%2,%3};\n"
        : "+f"(c[0]), "+f"(c[1]), "+f"(c[2]), "+f"(c[3])
        : "r"(a[0]), "r"(a[1]), "r"(a[2]), "r"(a[3]), "r"(b[0]), "r"(b[1]));
}
__device__ __forceinline__ void cpa16(void* dst, const void* src) {
    unsigned u = (unsigned)__cvta_generic_to_shared(dst);
    asm volatile("cp.async.cg.shared.global [%0], [%1], 16;\n" :: "r"(u), "l"(src));
}
__device__ __forceinline__ uint32_t h2pack(float x, float y) {
    uint32_t r;
    asm("cvt.rn.f16x2.f32 %0, %1, %2;" : "=r"(r) : "f"(y), "f"(x));
    return r;
}
// exp(x) for |x| <= 0.125: degree-4 Taylor, max rel err ~2.5e-7.
__device__ __forceinline__ float exp_small(float x) {
    float r = fmaf(x, 0.041666667f, 0.16666667f);
    r = fmaf(x, r, 0.5f);
    r = fmaf(x, r, 1.0f);
    r = fmaf(x, r, 1.0f);
    return r;
}

// ---------------------------------------------------------------------------
// Prep: convert x + concat weights to fp16 (float4 -> 4 halves per thread).
// ---------------------------------------------------------------------------
#define PREP_TOTAL 1425408

__global__ __launch_bounds__(256)
void prep_f16(const float* __restrict__ x,  const float* __restrict__ Wq,
              const float* __restrict__ Wk, const float* __restrict__ Wv1,
              const float* __restrict__ Wv2,const float* __restrict__ Wo)
{
    int idx = blockIdx.x * 256 + threadIdx.x;
    if (idx >= PREP_TOTAL) return;

    const float4* src;
    uint2* dst;
    if (idx < 786432)        { src = (const float4*)x   + idx;           dst = (uint2*)g_xh  + idx; }
    else if (idx < 1081344)  { int i = idx - 786432;  src = (const float4*)Wq  + i; dst = (uint2*)g_wh  + i; }
    else if (idx < 1179648)  { int i = idx - 1081344; src = (const float4*)Wk  + i; dst = (uint2*)g_wh  + 294912 + i; }
    else if (idx < 1228800)  { int i = idx - 1179648; src = (const float4*)Wv1 + i; dst = (uint2*)g_wh  + 393216 + i; }
    else if (idx < 1277952)  { int i = idx - 1228800; src = (const float4*)Wv2 + i; dst = (uint2*)g_wh  + 442368 + i; }
    else                     { int i = idx - 1277952; src = (const float4*)Wo  + i; dst = (uint2*)g_woh + i; }

    float4 v = *src;
    uint2 o;
    o.x = h2pack(v.x, v.y);
    o.y = h2pack(v.z, v.w);
    *dst = o;
}

// ---------------------------------------------------------------------------
// FP16 tensor-core GEMM: C[M,N](fp32) = A[M,K](fp16) * W[N,K]^T(fp16) (+bias)
// 128x128 block tile, TBK=64 (4 k16 chunks), 8 warps (2x4), 64x32 warp tile,
// cp.async double-buffered. smem stride 72 halves (conflict-free).
// ---------------------------------------------------------------------------
#define TBM 128
#define TBN 128
#define TBK 64
#define HST 72
#define GEMM_SMEM_BYTES (2 * 2 * TBM * HST * 2)   // 73728

__global__ __launch_bounds__(256, 2)
void gemm_f16(const __half* __restrict__ A, const __half* __restrict__ W,
              const float* __restrict__ bias, float* __restrict__ C,
              int M, int N, int K)
{
    extern __shared__ __half smh[];
    __half* As = smh;                      // [2][128][72]
    __half* Ws = smh + 2 * TBM * HST;      // [2][128][72]

    const int tid  = threadIdx.x;
    const int lane = tid & 31;
    const int warp = tid >> 5;
    const int wm   = (warp & 1) * 64;
    const int wn   = (warp >> 1) * 32;
    const int gid  = lane >> 2;
    const int tig  = lane & 3;

    const int m0 = blockIdx.y * TBM;
    const int n0 = blockIdx.x * TBN;

    // loader: A 1024 chunks (16B = 8 halves) + W 1024, 8 per thread
    auto load_stage = [&](int st, int k0) {
#pragma unroll
        for (int i = 0; i < 8; i++) {
            int idx = tid + i * 256;
            int r = (idx & 1023) >> 3;
            int c = (idx & 7) * 8;
            if (idx < 1024)
                cpa16(As + (st * TBM + r) * HST + c, A + (size_t)(m0 + r) * K + k0 + c);
            else
                cpa16(Ws + (st * TBN + r) * HST + c, W + (size_t)(n0 + r) * K + k0 + c);
        }
        asm volatile("cp.async.commit_group;\n" ::: "memory");
    };

    float acc[4][4][4];
#pragma unroll
    for (int i = 0; i < 4; i++)
#pragma unroll
        for (int j = 0; j < 4; j++)
#pragma unroll
            for (int l = 0; l < 4; l++) acc[i][j][l] = 0.f;

    const int nkt = K / TBK;
    load_stage(0, 0);

    for (int kt = 0; kt < nkt; kt++) {
        const int cur = kt & 1;
        if (kt + 1 < nkt) {
            load_stage(cur ^ 1, (kt + 1) * TBK);
            asm volatile("cp.async.wait_group 1;\n" ::: "memory");
        } else {
            asm volatile("cp.async.wait_group 0;\n" ::: "memory");
        }
        __syncthreads();

        const __half* Ab = As + cur * TBM * HST;
        const __half* Wb = Ws + cur * TBN * HST;

#pragma unroll
        for (int ktc = 0; ktc < 4; ktc++) {
            const int kb = ktc * 16 + 2 * tig;
            uint32_t bfr[4][2];
#pragma unroll
            for (int nt = 0; nt < 4; nt++) {
                const __half* wr = Wb + (wn + nt * 8 + gid) * HST + kb;
                bfr[nt][0] = *reinterpret_cast<const uint32_t*>(wr);
                bfr[nt][1] = *reinterpret_cast<const uint32_t*>(wr + 8);
            }
#pragma unroll
            for (int mt = 0; mt < 4; mt++) {
                const __half* ar = Ab + (wm + mt * 16 + gid) * HST + kb;
                uint32_t af[4];
                af[0] = *reinterpret_cast<const uint32_t*>(ar);
                af[1] = *reinterpret_cast<const uint32_t*>(ar + 8 * HST);
                af[2] = *reinterpret_cast<const uint32_t*>(ar + 8);
                af[3] = *reinterpret_cast<const uint32_t*>(ar + 8 * HST + 8);
#pragma unroll
                for (int nt = 0; nt < 4; nt++)
                    mma_f16(acc[mt][nt], af, bfr[nt]);
            }
        }
        __syncthreads();
    }

#pragma unroll
    for (int mt = 0; mt < 4; mt++) {
        int m = m0 + wm + mt * 16 + gid;
#pragma unroll
        for (int nt = 0; nt < 4; nt++) {
            int n = n0 + wn + nt * 8 + 2 * tig;
            float b0 = bias ? bias[n] : 0.f;
            float b1 = bias ? bias[n + 1] : 0.f;
            float2 r0 = make_float2(acc[mt][nt][0] + b0, acc[mt][nt][1] + b1);
            float2 r1 = make_float2(acc[mt][nt][2] + b0, acc[mt][nt][3] + b1);
            *reinterpret_cast<float2*>(C + (size_t)m * N + n) = r0;
            *reinterpret_cast<float2*>(C + (size_t)(m + 8) * N + n) = r1;
        }
    }
}

// ---------------------------------------------------------------------------
// 2D RoPE + qk-norm. Reads g_proj fp32 q|k (cols 0..2047), writes fp16 g_qkh.
// ---------------------------------------------------------------------------
__global__ __launch_bounds__(256)
void rope_norm(int total_vec)
{
    const int gw   = (blockIdx.x * blockDim.x + threadIdx.x) >> 5;
    const int lane = threadIdx.x & 31;
    if (gw >= total_vec) return;

    const int row = gw >> 5;
    const int vec = gw & 31;
    const int n   = row & (N_ - 1);
    const float ph = (float)(n >> 5);
    const float pw = (float)(n & 31);

    const float* p = g_proj + (size_t)row * PROJ_N + vec * 64;
    float x0 = p[lane];
    float x1 = p[lane + 32];

    float inv = exp2f((float)lane * -0.4152410118609203f);
    float t0 = ph * inv, t1 = pw * inv;
    float c0, s0, c1, s1;
    __sincosf(t0, &s0, &c0);
    __sincosf(t1, &s1, &c1);

    float px0 = __shfl_xor_sync(0xffffffffu, x0, 1);
    float px1 = __shfl_xor_sync(0xffffffffu, x1, 1);
    float r0 = (lane & 1) ? px0 : -px0;
    float r1 = (lane & 1) ? px1 : -px1;

    float o0 = x0 * c0 + r0 * s0;
    float o1 = x1 * c1 + r1 * s1;

    float ss = o0 * o0 + o1 * o1;
#pragma unroll
    for (int o = 16; o; o >>= 1) ss += __shfl_xor_sync(0xffffffffu, ss, o);
    float sc = 1.f / (sqrtf(ss) + 1e-6f);

    __half* q = g_qkh + (size_t)row * 2048 + vec * 64;
    q[lane]      = __float2half_rn(o0 * sc);
    q[lane + 32] = __float2half_rn(o1 * sc);
}

// ---------------------------------------------------------------------------
// V transpose + fp16 convert: g_proj v cols -> g_vt[bks][d(64)][key(1024)].
// ---------------------------------------------------------------------------
__global__ __launch_bounds__(256)
void v_transpose()
{
    __shared__ float tile[32][65];

    const int bks    = blockIdx.x >> 5;
    const int keyblk = blockIdx.x & 31;
    const int b    = bks >> 3;
    const int kh   = (bks >> 1) & 3;
    const int side = bks & 1;
    const int col0 = OFF_V1 + side * 256 + kh * 64;
    const int tid  = threadIdx.x;

    {
        int key = tid >> 3, seg = tid & 7;
        const float* src = g_proj + (size_t)(b * N_ + keyblk * 32 + key) * PROJ_N + col0 + seg * 8;
        float4 l0 = *reinterpret_cast<const float4*>(src);
        float4 l1 = *reinterpret_cast<const float4*>(src + 4);
        tile[key][seg * 8 + 0] = l0.x; tile[key][seg * 8 + 1] = l0.y;
        tile[key][seg * 8 + 2] = l0.z; tile[key][seg * 8 + 3] = l0.w;
        tile[key][seg * 8 + 4] = l1.x; tile[key][seg * 8 + 5] = l1.y;
        tile[key][seg * 8 + 6] = l1.z; tile[key][seg * 8 + 7] = l1.w;
    }
    __syncthreads();

    {
        int d = tid >> 2, kq = tid & 3;
        uint32_t w[4];
#pragma unroll
        for (int j = 0; j < 4; j++)
            w[j] = h2pack(tile[kq * 8 + 2 * j][d], tile[kq * 8 + 2 * j + 1][d]);
        __half* dst = g_vt + (size_t)bks * 65536 + d * 1024 + keyblk * 32 + kq * 8;
        *reinterpret_cast<uint4*>(dst) = make_uint4(w[0], w[1], w[2], w[3]);
    }
}

// ---------------------------------------------------------------------------
// fp16 tensor-core windowed attention (round-13 version, unchanged).
// ---------------------------------------------------------------------------
#define KST 72
#define VST 40
#define H_STAGE (32 * KST + 64 * VST)
#define ATT_SMEM_BYTES (2 * H_STAGE * 2)

__global__ __launch_bounds__(96, 3)
void attn_tc(const float* __restrict__ lambda_p)
{
    extern __shared__ __half smh[];

    const int tid  = threadIdx.x;
    const int lane = tid & 31;
    const int warp = tid >> 5;
    const int gid  = lane >> 2;
    const int tig  = lane & 3;

    const int blk  = blockIdx.x;
    const int ph   = blk & 31;
    const int side = (blk >> 5) & 1;
    const int kh   = (blk >> 6) & 3;
    const int b    = blk >> 8;
    const int bks  = ((b * 4 + kh) * 2 + side);

    const int h = kh * 3 + warp;

    const int rlo = max(ph - WIN_, 0);
    const int rhi = min(ph + WIN_, SIDE_ - 1);
    const int nit = rhi - rlo + 1;

    const int kcol = 1536 + side * 256 + kh * 64;

    uint32_t mbits = 0;
#pragma unroll
    for (int mt = 0; mt < 2; mt++)
#pragma unroll
        for (int nt = 0; nt < 4; nt++)
#pragma unroll
            for (int c = 0; c < 4; c++) {
                int pwq = mt * 16 + gid + ((c >> 1) << 3);
                int ck  = nt * 8 + 2 * tig + (c & 1);
                int d = pwq - ck; d = (d < 0) ? -d : d;
                if (d <= WIN_) mbits |= 1u << (mt * 16 + nt * 4 + c);
            }

    auto load_stage = [&](int st, int r) {
#pragma unroll
        for (int i = 0; i < 6; i++) {
            int idx = tid + i * 96;
            if (idx < 256) {
                int key = idx >> 3, j = idx & 7;
                const __half* src = g_qkh + (size_t)(b * N_ + r * 32 + key) * 2048 + kcol + j * 8;
                cpa16(smh + st * H_STAGE + key * KST + j * 8, src);
            } else if (idx < 512) {
                int i2 = idx - 256;
                int d = i2 >> 2, j = i2 & 3;
                const __half* src = g_vt + (size_t)bks * 65536 + d * 1024 + r * 32 + j * 8;
                cpa16(smh + st * H_STAGE + 32 * KST + d * VST + j * 8, src);
            }
        }
        asm volatile("cp.async.commit_group;\n" ::: "memory");
    };

    load_stage(0, rlo);

    uint32_t qf[2][4][4];
    {
        const __half* qb = g_qkh + (size_t)(b * N_ + ph * 32) * 2048 + side * 768 + h * 64;
#pragma unroll
        for (int mt = 0; mt < 2; mt++) {
            const __half* q0 = qb + (size_t)(mt * 16 + gid) * 2048;
            const __half* q1 = q0 + (size_t)8 * 2048;
#pragma unroll
            for (int ktc = 0; ktc < 4; ktc++) {
                qf[mt][ktc][0] = *reinterpret_cast<const uint32_t*>(q0 + ktc * 16 + 2 * tig);
                qf[mt][ktc][1] = *reinterpret_cast<const uint32_t*>(q1 + ktc * 16 + 2 * tig);
                qf[mt][ktc][2] = *reinterpret_cast<const uint32_t*>(q0 + ktc * 16 + 8 + 2 * tig);
                qf[mt][ktc][3] = *reinterpret_cast<const uint32_t*>(q1 + ktc * 16 + 8 + 2 * tig);
            }
        }
    }

    float o[2][8][4];
#pragma unroll
    for (int mt = 0; mt < 2; mt++)
#pragma unroll
        for (int nt = 0; nt < 8; nt++)
#pragma unroll
            for (int c = 0; c < 4; c++) o[mt][nt][c] = 0.f;

    float l_[2][2] = {{0.f, 0.f}, {0.f, 0.f}};

    asm volatile("cp.async.wait_group 0;\n" ::: "memory");
    __syncthreads();

    for (int it = 0; it < nit; it++) {
        const int cur = it & 1;
        if (it + 1 < nit) load_stage(cur ^ 1, rlo + it + 1);

        const __half* K = smh + cur * H_STAGE;
        const __half* V = K + 32 * KST;

        float s[2][4][4];
#pragma unroll
        for (int mt = 0; mt < 2; mt++)
#pragma unroll
            for (int nt = 0; nt < 4; nt++)
#pragma unroll
                for (int c = 0; c < 4; c++) s[mt][nt][c] = 0.f;

#pragma unroll
        for (int ktc = 0; ktc < 4; ktc++) {
            uint32_t bf[4][2];
#pragma unroll
            for (int nt = 0; nt < 4; nt++) {
                const __half* kr = K + (nt * 8 + gid) * KST + ktc * 16 + 2 * tig;
                bf[nt][0] = *reinterpret_cast<const uint32_t*>(kr);
                bf[nt][1] = *reinterpret_cast<const uint32_t*>(kr + 8);
            }
#pragma unroll
            for (int mt = 0; mt < 2; mt++)
#pragma unroll
                for (int nt = 0; nt < 4; nt++) {
                    if ((mt == 0 && nt == 3) || (mt == 1 && nt == 0)) continue;
                    mma_f16(s[mt][nt], qf[mt][ktc], bf[nt]);
                }
        }

        uint32_t paf[2][2][4];
#pragma unroll
        for (int mt = 0; mt < 2; mt++)
#pragma unroll
            for (int k2 = 0; k2 < 2; k2++)
#pragma unroll
                for (int q = 0; q < 4; q++) paf[mt][k2][q] = 0;

#pragma unroll
        for (int mt = 0; mt < 2; mt++)
#pragma unroll
            for (int nt = 0; nt < 4; nt++) {
                if ((mt == 0 && nt == 3) || (mt == 1 && nt == 0)) continue;
                float p0 = exp_small(s[mt][nt][0] * 0.125f);
                float p1 = exp_small(s[mt][nt][1] * 0.125f);
                float p2 = exp_small(s[mt][nt][2] * 0.125f);
                float p3 = exp_small(s[mt][nt][3] * 0.125f);
                p0 = (mbits >> (mt * 16 + nt * 4 + 0)) & 1 ? p0 : 0.f;
                p1 = (mbits >> (mt * 16 + nt * 4 + 1)) & 1 ? p1 : 0.f;
                p2 = (mbits >> (mt * 16 + nt * 4 + 2)) & 1 ? p2 : 0.f;
                p3 = (mbits >> (mt * 16 + nt * 4 + 3)) & 1 ? p3 : 0.f;
                l_[mt][0] += p0 + p1;
                l_[mt][1] += p2 + p3;
                paf[mt][nt >> 1][(nt & 1) * 2 + 0] = h2pack(p0, p1);
                paf[mt][nt >> 1][(nt & 1) * 2 + 1] = h2pack(p2, p3);
            }

#pragma unroll
        for (int k2 = 0; k2 < 2; k2++) {
#pragma unroll
            for (int nt = 0; nt < 8; nt++) {
                const __half* vr = V + (nt * 8 + gid) * VST + k2 * 16 + 2 * tig;
                uint32_t bf[2];
                bf[0] = *reinterpret_cast<const uint32_t*>(vr);
                bf[1] = *reinterpret_cast<const uint32_t*>(vr + 8);
                mma_f16(o[0][nt], paf[0][k2], bf);
                mma_f16(o[1][nt], paf[1][k2], bf);
            }
        }

        asm volatile("cp.async.wait_group 0;\n" ::: "memory");
        __syncthreads();
    }

#pragma unroll
    for (int mt = 0; mt < 2; mt++)
#pragma unroll
        for (int hf = 0; hf < 2; hf++) {
            float r = l_[mt][hf];
            r += __shfl_xor_sync(0xffffffffu, r, 1);
            r += __shfl_xor_sync(0xffffffffu, r, 2);
            l_[mt][hf] = r;
        }

    float lam = side ? log1pf(__expf(lambda_p[h])) : 1.f;
    float inv[2][2] = {{lam / l_[0][0], lam / l_[0][1]},
                       {lam / l_[1][0], lam / l_[1][1]}};

    float* dst = g_od + ((size_t)side * M_ROWS + (size_t)(b * N_ + ph * 32)) * 768 + h * 64;
#pragma unroll
    for (int mt = 0; mt < 2; mt++)
#pragma unroll
        for (int nt = 0; nt < 8; nt++) {
            int r0 = mt * 16 + gid, r1 = r0 + 8, cc = nt * 8 + 2 * tig;
            float2 v0, v1;
            v0.x = o[mt][nt][0] * inv[mt][0];
            v0.y = o[mt][nt][1] * inv[mt][0];
            v1.x = o[mt][nt][2] * inv[mt][1];
            v1.y = o[mt][nt][3] * inv[mt][1];
            *reinterpret_cast<float2*>(dst + (size_t)r0 * 768 + cc) = v0;
            *reinterpret_cast<float2*>(dst + (size_t)r1 * 768 + cc) = v1;
        }
}

// ---------------------------------------------------------------------------
// Combine: ctxh = fp16(O1 - O2_scaled), 4 floats -> 4 halves per thread.
// ---------------------------------------------------------------------------
#define CTX_F4 (M_ROWS * DIM_ / 4)   // 786432

__global__ __launch_bounds__(256)
void combine_o()
{
    int idx = blockIdx.x * 256 + threadIdx.x;
    if (idx >= CTX_F4) return;
    const float4* o1 = reinterpret_cast<const float4*>(g_od);
    const float4* o2 = reinterpret_cast<const float4*>(g_od + (size_t)M_ROWS * DIM_);
    float4 a = o1[idx], c = o2[idx];
    uint2 r;
    r.x = h2pack(a.x - c.x, a.y - c.y);
    r.y = h2pack(a.z - c.z, a.w - c.w);
    reinterpret_cast<uint2*>(g_ctxh)[idx] = r;
}

// ---------------------------------------------------------------------------
// Launch
// ---------------------------------------------------------------------------
extern "C" void kernel_launch(void* const* d_in, const int* in_sizes, int n_in,
                              void* d_out, int out_size)
{
    const float* x      = (const float*)d_in[0];
    const float* Wq     = (const float*)d_in[1];
    const float* Wk     = (const float*)d_in[2];
    const float* Wv1    = (const float*)d_in[3];
    const float* Wv2    = (const float*)d_in[4];
    const float* lam_p  = (const float*)d_in[5];
    const float* Wo     = (const float*)d_in[6];
    const float* bo     = (const float*)d_in[7];
    float* out = (float*)d_out;

    __half *gxh, *gwh, *gwoh, *ctxh;
    float *proj;
    cudaGetSymbolAddress((void**)&gxh,  g_xh);
    cudaGetSymbolAddress((void**)&gwh,  g_wh);
    cudaGetSymbolAddress((void**)&gwoh, g_woh);
    cudaGetSymbolAddress((void**)&proj, g_proj);
    cudaGetSymbolAddress((void**)&ctxh, g_ctxh);

    cudaFuncSetAttribute(gemm_f16, cudaFuncAttributeMaxDynamicSharedMemorySize,
                         GEMM_SMEM_BYTES);
    cudaFuncSetAttribute(attn_tc, cudaFuncAttributeMaxDynamicSharedMemorySize,
                         ATT_SMEM_BYTES);

    // fp16 conversion + weight concat
    prep_f16<<<(PREP_TOTAL + 255) / 256, 256>>>(x, Wq, Wk, Wv1, Wv2, Wo);

    // fused projections: one fp16 GEMM [4096 x 2560 x 768] -> fp32 g_proj
    gemm_f16<<<dim3(PROJ_N / TBN, M_ROWS / TBM), 256, GEMM_SMEM_BYTES>>>(
        gxh, gwh, nullptr, proj, M_ROWS, PROJ_N, DIM_);

    // RoPE + qk-norm -> fp16 g_qkh
    {
        int vec = M_ROWS * 32;
        rope_norm<<<(vec * 32 + 255) / 256, 256>>>(vec);
    }

    // V transpose + fp16 convert -> g_vt
    v_transpose<<<1024, 256>>>();

    // fp16 tensor-core windowed attention
    attn_tc<<<B_ * KV_ * 2 * SIDE_, 96, ATT_SMEM_BYTES>>>(lam_p);

    // differential combine -> fp16 ctx
    combine_o<<<(CTX_F4 + 255) / 256, 256>>>();

    // output projection + bias (fp16 GEMM, fp32 out)
    gemm_f16<<<dim3(DIM_ / TBN, M_ROWS / TBM), 256, GEMM_SMEM_BYTES>>>(
        ctxh, gwoh, bo, out, M_ROWS, DIM_, DIM_);
}

// round 15
// speedup vs baseline: 1.7422x; 1.0025x over previous
#include <cuda_runtime.h>
#include <cuda_fp16.h>
#include <math.h>
#include <stdint.h>

// Problem constants
#define B_    4
#define N_    1024
#define DIM_  768
#define H_    12
#define KV_   4
#define D_    64
#define SIDE_ 32
#define WIN_  8
#define M_ROWS (B_ * N_)       // 4096

// Fused projection layout: [row][2560] = q(0..1535) | k(1536..2047) | v1(2048..2303) | v2(2304..2559)
#define PROJ_N 2560
#define OFF_V1 2048

// ---------------------------------------------------------------------------
// Scratch (all intermediates fp16)
// ---------------------------------------------------------------------------
__device__ __half g_xh  [M_ROWS * DIM_];
__device__ __half g_wh  [PROJ_N * DIM_];
__device__ __half g_woh [DIM_ * DIM_];
__device__ __half g_proj[M_ROWS * PROJ_N];        // fp16 projections (20 MB)
__device__ __half g_qkh [M_ROWS * 2048];          // fp16 roped q|k
__device__ __half g_vt  [32 * 64 * 1024];         // fp16 V transposed: [bks][d][key]
__device__ __half g_odh [2 * M_ROWS * DIM_];      // fp16 per-side normalized O
__device__ __half g_ctxh[M_ROWS * DIM_];          // fp16 ctx

// ---------------------------------------------------------------------------
// PTX helpers
// ---------------------------------------------------------------------------
__device__ __forceinline__ void mma_f16(float* c, const uint32_t* a, const uint32_t* b) {
    asm volatile(
        "mma.sync.aligned.m16n8k16.row.col.f32.f16.f16.f32 "
        "{%0,%1,%2,%3}, {%4,%5,%6,%7}, {%8,%9}, {%0,%1,%2,%3};\n"
        : "+f"(c[0]), "+f"(c[1]), "+f"(c[2]), "+f"(c[3])
        : "r"(a[0]), "r"(a[1]), "r"(a[2]), "r"(a[3]), "r"(b[0]), "r"(b[1]));
}
__device__ __forceinline__ void cpa16(void* dst, const void* src) {
    unsigned u = (unsigned)__cvta_generic_to_shared(dst);
    asm volatile("cp.async.cg.shared.global [%0], [%1], 16;\n" :: "r"(u), "l"(src));
}
__device__ __forceinline__ uint32_t h2pack(float x, float y) {
    uint32_t r;
    asm("cvt.rn.f16x2.f32 %0, %1, %2;" : "=r"(r) : "f"(y), "f"(x));
    return r;
}
// exp(x) for |x| <= 0.125: degree-4 Taylor, max rel err ~2.5e-7.
__device__ __forceinline__ float exp_small(float x) {
    float r = fmaf(x, 0.041666667f, 0.16666667f);
    r = fmaf(x, r, 0.5f);
    r = fmaf(x, r, 1.0f);
    r = fmaf(x, r, 1.0f);
    return r;
}

// ---------------------------------------------------------------------------
// Prep: convert x + concat weights to fp16.
// ---------------------------------------------------------------------------
#define PREP_TOTAL 1425408

__global__ __launch_bounds__(256)
void prep_f16(const float* __restrict__ x,  const float* __restrict__ Wq,
              const float* __restrict__ Wk, const float* __restrict__ Wv1,
              const float* __restrict__ Wv2,const float* __restrict__ Wo)
{
    int idx = blockIdx.x * 256 + threadIdx.x;
    if (idx >= PREP_TOTAL) return;

    const float4* src;
    uint2* dst;
    if (idx < 786432)        { src = (const float4*)x   + idx;           dst = (uint2*)g_xh  + idx; }
    else if (idx < 1081344)  { int i = idx - 786432;  src = (const float4*)Wq  + i; dst = (uint2*)g_wh  + i; }
    else if (idx < 1179648)  { int i = idx - 1081344; src = (const float4*)Wk  + i; dst = (uint2*)g_wh  + 294912 + i; }
    else if (idx < 1228800)  { int i = idx - 1179648; src = (const float4*)Wv1 + i; dst = (uint2*)g_wh  + 393216 + i; }
    else if (idx < 1277952)  { int i = idx - 1228800; src = (const float4*)Wv2 + i; dst = (uint2*)g_wh  + 442368 + i; }
    else                     { int i = idx - 1277952; src = (const float4*)Wo  + i; dst = (uint2*)g_woh + i; }

    float4 v = *src;
    uint2 o;
    o.x = h2pack(v.x, v.y);
    o.y = h2pack(v.z, v.w);
    *dst = o;
}

// ---------------------------------------------------------------------------
// FP16 tensor-core GEMM: acc fp32; output fp16 (OUTH=true) or fp32.
// 128x128 block tile, TBK=64, 8 warps (2x4), 64x32 warp tile, cp.async x2.
// ---------------------------------------------------------------------------
#define TBM 128
#define TBN 128
#define TBK 64
#define HST 72
#define GEMM_SMEM_BYTES (2 * 2 * TBM * HST * 2)   // 73728

template <bool OUTH>
__global__ __launch_bounds__(256, 2)
void gemm_f16(const __half* __restrict__ A, const __half* __restrict__ W,
              const float* __restrict__ bias, void* __restrict__ Cv,
              int M, int N, int K)
{
    extern __shared__ __half smh[];
    __half* As = smh;
    __half* Ws = smh + 2 * TBM * HST;

    const int tid  = threadIdx.x;
    const int lane = tid & 31;
    const int warp = tid >> 5;
    const int wm   = (warp & 1) * 64;
    const int wn   = (warp >> 1) * 32;
    const int gid  = lane >> 2;
    const int tig  = lane & 3;

    const int m0 = blockIdx.y * TBM;
    const int n0 = blockIdx.x * TBN;

    auto load_stage = [&](int st, int k0) {
#pragma unroll
        for (int i = 0; i < 8; i++) {
            int idx = tid + i * 256;
            int r = (idx & 1023) >> 3;
            int c = (idx & 7) * 8;
            if (idx < 1024)
                cpa16(As + (st * TBM + r) * HST + c, A + (size_t)(m0 + r) * K + k0 + c);
            else
                cpa16(Ws + (st * TBN + r) * HST + c, W + (size_t)(n0 + r) * K + k0 + c);
        }
        asm volatile("cp.async.commit_group;\n" ::: "memory");
    };

    float acc[4][4][4];
#pragma unroll
    for (int i = 0; i < 4; i++)
#pragma unroll
        for (int j = 0; j < 4; j++)
#pragma unroll
            for (int l = 0; l < 4; l++) acc[i][j][l] = 0.f;

    const int nkt = K / TBK;
    load_stage(0, 0);

    for (int kt = 0; kt < nkt; kt++) {
        const int cur = kt & 1;
        if (kt + 1 < nkt) {
            load_stage(cur ^ 1, (kt + 1) * TBK);
            asm volatile("cp.async.wait_group 1;\n" ::: "memory");
        } else {
            asm volatile("cp.async.wait_group 0;\n" ::: "memory");
        }
        __syncthreads();

        const __half* Ab = As + cur * TBM * HST;
        const __half* Wb = Ws + cur * TBN * HST;

#pragma unroll
        for (int ktc = 0; ktc < 4; ktc++) {
            const int kb = ktc * 16 + 2 * tig;
            uint32_t bfr[4][2];
#pragma unroll
            for (int nt = 0; nt < 4; nt++) {
                const __half* wr = Wb + (wn + nt * 8 + gid) * HST + kb;
                bfr[nt][0] = *reinterpret_cast<const uint32_t*>(wr);
                bfr[nt][1] = *reinterpret_cast<const uint32_t*>(wr + 8);
            }
#pragma unroll
            for (int mt = 0; mt < 4; mt++) {
                const __half* ar = Ab + (wm + mt * 16 + gid) * HST + kb;
                uint32_t af[4];
                af[0] = *reinterpret_cast<const uint32_t*>(ar);
                af[1] = *reinterpret_cast<const uint32_t*>(ar + 8 * HST);
                af[2] = *reinterpret_cast<const uint32_t*>(ar + 8);
                af[3] = *reinterpret_cast<const uint32_t*>(ar + 8 * HST + 8);
#pragma unroll
                for (int nt = 0; nt < 4; nt++)
                    mma_f16(acc[mt][nt], af, bfr[nt]);
            }
        }
        __syncthreads();
    }

#pragma unroll
    for (int mt = 0; mt < 4; mt++) {
        int m = m0 + wm + mt * 16 + gid;
#pragma unroll
        for (int nt = 0; nt < 4; nt++) {
            int n = n0 + wn + nt * 8 + 2 * tig;
            float b0 = bias ? bias[n] : 0.f;
            float b1 = bias ? bias[n + 1] : 0.f;
            float c00 = acc[mt][nt][0] + b0, c01 = acc[mt][nt][1] + b1;
            float c10 = acc[mt][nt][2] + b0, c11 = acc[mt][nt][3] + b1;
            if (OUTH) {
                __half* C = (__half*)Cv;
                *reinterpret_cast<uint32_t*>(C + (size_t)m * N + n)       = h2pack(c00, c01);
                *reinterpret_cast<uint32_t*>(C + (size_t)(m + 8) * N + n) = h2pack(c10, c11);
            } else {
                float* C = (float*)Cv;
                *reinterpret_cast<float2*>(C + (size_t)m * N + n)       = make_float2(c00, c01);
                *reinterpret_cast<float2*>(C + (size_t)(m + 8) * N + n) = make_float2(c10, c11);
            }
        }
    }
}

// ---------------------------------------------------------------------------
// 2D RoPE + qk-norm. Reads fp16 g_proj q|k, computes fp32, writes fp16 g_qkh.
// ---------------------------------------------------------------------------
__global__ __launch_bounds__(256)
void rope_norm(int total_vec)
{
    const int gw   = (blockIdx.x * blockDim.x + threadIdx.x) >> 5;
    const int lane = threadIdx.x & 31;
    if (gw >= total_vec) return;

    const int row = gw >> 5;
    const int vec = gw & 31;
    const int n   = row & (N_ - 1);
    const float ph = (float)(n >> 5);
    const float pw = (float)(n & 31);

    const __half* p = g_proj + (size_t)row * PROJ_N + vec * 64;
    float x0 = __half2float(p[lane]);
    float x1 = __half2float(p[lane + 32]);

    float inv = exp2f((float)lane * -0.4152410118609203f);
    float t0 = ph * inv, t1 = pw * inv;
    float c0, s0, c1, s1;
    __sincosf(t0, &s0, &c0);
    __sincosf(t1, &s1, &c1);

    float px0 = __shfl_xor_sync(0xffffffffu, x0, 1);
    float px1 = __shfl_xor_sync(0xffffffffu, x1, 1);
    float r0 = (lane & 1) ? px0 : -px0;
    float r1 = (lane & 1) ? px1 : -px1;

    float o0 = x0 * c0 + r0 * s0;
    float o1 = x1 * c1 + r1 * s1;

    float ss = o0 * o0 + o1 * o1;
#pragma unroll
    for (int o = 16; o; o >>= 1) ss += __shfl_xor_sync(0xffffffffu, ss, o);
    float sc = 1.f / (sqrtf(ss) + 1e-6f);

    __half* q = g_qkh + (size_t)row * 2048 + vec * 64;
    q[lane]      = __float2half_rn(o0 * sc);
    q[lane + 32] = __float2half_rn(o1 * sc);
}

// ---------------------------------------------------------------------------
// V transpose: fp16 g_proj v cols -> fp16 g_vt[bks][d(64)][key(1024)].
// ---------------------------------------------------------------------------
__global__ __launch_bounds__(256)
void v_transpose()
{
    __shared__ float tile[32][65];

    const int bks    = blockIdx.x >> 5;
    const int keyblk = blockIdx.x & 31;
    const int b    = bks >> 3;
    const int kh   = (bks >> 1) & 3;
    const int side = bks & 1;
    const int col0 = OFF_V1 + side * 256 + kh * 64;
    const int tid  = threadIdx.x;

    {
        int key = tid >> 3, seg = tid & 7;
        const __half* src = g_proj + (size_t)(b * N_ + keyblk * 32 + key) * PROJ_N + col0 + seg * 8;
        uint4 raw = *reinterpret_cast<const uint4*>(src);
        const __half2* hp = reinterpret_cast<const __half2*>(&raw);
#pragma unroll
        for (int j = 0; j < 4; j++) {
            float2 f = __half22float2(hp[j]);
            tile[key][seg * 8 + 2 * j]     = f.x;
            tile[key][seg * 8 + 2 * j + 1] = f.y;
        }
    }
    __syncthreads();

    {
        int d = tid >> 2, kq = tid & 3;
        uint32_t w[4];
#pragma unroll
        for (int j = 0; j < 4; j++)
            w[j] = h2pack(tile[kq * 8 + 2 * j][d], tile[kq * 8 + 2 * j + 1][d]);
        __half* dst = g_vt + (size_t)bks * 65536 + d * 1024 + keyblk * 32 + kq * 8;
        *reinterpret_cast<uint4*>(dst) = make_uint4(w[0], w[1], w[2], w[3]);
    }
}

// ---------------------------------------------------------------------------
// fp16 tensor-core windowed attention (round-13 core; fp16 O output).
// ---------------------------------------------------------------------------
#define KST 72
#define VST 40
#define H_STAGE (32 * KST + 64 * VST)
#define ATT_SMEM_BYTES (2 * H_STAGE * 2)

__global__ __launch_bounds__(96, 3)
void attn_tc(const float* __restrict__ lambda_p)
{
    extern __shared__ __half smh[];

    const int tid  = threadIdx.x;
    const int lane = tid & 31;
    const int warp = tid >> 5;
    const int gid  = lane >> 2;
    const int tig  = lane & 3;

    const int blk  = blockIdx.x;
    const int ph   = blk & 31;
    const int side = (blk >> 5) & 1;
    const int kh   = (blk >> 6) & 3;
    const int b    = blk >> 8;
    const int bks  = ((b * 4 + kh) * 2 + side);

    const int h = kh * 3 + warp;

    const int rlo = max(ph - WIN_, 0);
    const int rhi = min(ph + WIN_, SIDE_ - 1);
    const int nit = rhi - rlo + 1;

    const int kcol = 1536 + side * 256 + kh * 64;

    uint32_t mbits = 0;
#pragma unroll
    for (int mt = 0; mt < 2; mt++)
#pragma unroll
        for (int nt = 0; nt < 4; nt++)
#pragma unroll
            for (int c = 0; c < 4; c++) {
                int pwq = mt * 16 + gid + ((c >> 1) << 3);
                int ck  = nt * 8 + 2 * tig + (c & 1);
                int d = pwq - ck; d = (d < 0) ? -d : d;
                if (d <= WIN_) mbits |= 1u << (mt * 16 + nt * 4 + c);
            }

    auto load_stage = [&](int st, int r) {
#pragma unroll
        for (int i = 0; i < 6; i++) {
            int idx = tid + i * 96;
            if (idx < 256) {
                int key = idx >> 3, j = idx & 7;
                const __half* src = g_qkh + (size_t)(b * N_ + r * 32 + key) * 2048 + kcol + j * 8;
                cpa16(smh + st * H_STAGE + key * KST + j * 8, src);
            } else if (idx < 512) {
                int i2 = idx - 256;
                int d = i2 >> 2, j = i2 & 3;
                const __half* src = g_vt + (size_t)bks * 65536 + d * 1024 + r * 32 + j * 8;
                cpa16(smh + st * H_STAGE + 32 * KST + d * VST + j * 8, src);
            }
        }
        asm volatile("cp.async.commit_group;\n" ::: "memory");
    };

    load_stage(0, rlo);

    uint32_t qf[2][4][4];
    {
        const __half* qb = g_qkh + (size_t)(b * N_ + ph * 32) * 2048 + side * 768 + h * 64;
#pragma unroll
        for (int mt = 0; mt < 2; mt++) {
            const __half* q0 = qb + (size_t)(mt * 16 + gid) * 2048;
            const __half* q1 = q0 + (size_t)8 * 2048;
#pragma unroll
            for (int ktc = 0; ktc < 4; ktc++) {
                qf[mt][ktc][0] = *reinterpret_cast<const uint32_t*>(q0 + ktc * 16 + 2 * tig);
                qf[mt][ktc][1] = *reinterpret_cast<const uint32_t*>(q1 + ktc * 16 + 2 * tig);
                qf[mt][ktc][2] = *reinterpret_cast<const uint32_t*>(q0 + ktc * 16 + 8 + 2 * tig);
                qf[mt][ktc][3] = *reinterpret_cast<const uint32_t*>(q1 + ktc * 16 + 8 + 2 * tig);
            }
        }
    }

    float o[2][8][4];
#pragma unroll
    for (int mt = 0; mt < 2; mt++)
#pragma unroll
        for (int nt = 0; nt < 8; nt++)
#pragma unroll
            for (int c = 0; c < 4; c++) o[mt][nt][c] = 0.f;

    float l_[2][2] = {{0.f, 0.f}, {0.f, 0.f}};

    asm volatile("cp.async.wait_group 0;\n" ::: "memory");
    __syncthreads();

    for (int it = 0; it < nit; it++) {
        const int cur = it & 1;
        if (it + 1 < nit) load_stage(cur ^ 1, rlo + it + 1);

        const __half* K = smh + cur * H_STAGE;
        const __half* V = K + 32 * KST;

        float s[2][4][4];
#pragma unroll
        for (int mt = 0; mt < 2; mt++)
#pragma unroll
            for (int nt = 0; nt < 4; nt++)
#pragma unroll
                for (int c = 0; c < 4; c++) s[mt][nt][c] = 0.f;

#pragma unroll
        for (int ktc = 0; ktc < 4; ktc++) {
            uint32_t bf[4][2];
#pragma unroll
            for (int nt = 0; nt < 4; nt++) {
                const __half* kr = K + (nt * 8 + gid) * KST + ktc * 16 + 2 * tig;
                bf[nt][0] = *reinterpret_cast<const uint32_t*>(kr);
                bf[nt][1] = *reinterpret_cast<const uint32_t*>(kr + 8);
            }
#pragma unroll
            for (int mt = 0; mt < 2; mt++)
#pragma unroll
                for (int nt = 0; nt < 4; nt++) {
                    if ((mt == 0 && nt == 3) || (mt == 1 && nt == 0)) continue;
                    mma_f16(s[mt][nt], qf[mt][ktc], bf[nt]);
                }
        }

        uint32_t paf[2][2][4];
#pragma unroll
        for (int mt = 0; mt < 2; mt++)
#pragma unroll
            for (int k2 = 0; k2 < 2; k2++)
#pragma unroll
                for (int q = 0; q < 4; q++) paf[mt][k2][q] = 0;

#pragma unroll
        for (int mt = 0; mt < 2; mt++)
#pragma unroll
            for (int nt = 0; nt < 4; nt++) {
                if ((mt == 0 && nt == 3) || (mt == 1 && nt == 0)) continue;
                float p0 = exp_small(s[mt][nt][0] * 0.125f);
                float p1 = exp_small(s[mt][nt][1] * 0.125f);
                float p2 = exp_small(s[mt][nt][2] * 0.125f);
                float p3 = exp_small(s[mt][nt][3] * 0.125f);
                p0 = (mbits >> (mt * 16 + nt * 4 + 0)) & 1 ? p0 : 0.f;
                p1 = (mbits >> (mt * 16 + nt * 4 + 1)) & 1 ? p1 : 0.f;
                p2 = (mbits >> (mt * 16 + nt * 4 + 2)) & 1 ? p2 : 0.f;
                p3 = (mbits >> (mt * 16 + nt * 4 + 3)) & 1 ? p3 : 0.f;
                l_[mt][0] += p0 + p1;
                l_[mt][1] += p2 + p3;
                paf[mt][nt >> 1][(nt & 1) * 2 + 0] = h2pack(p0, p1);
                paf[mt][nt >> 1][(nt & 1) * 2 + 1] = h2pack(p2, p3);
            }

#pragma unroll
        for (int k2 = 0; k2 < 2; k2++) {
#pragma unroll
            for (int nt = 0; nt < 8; nt++) {
                const __half* vr = V + (nt * 8 + gid) * VST + k2 * 16 + 2 * tig;
                uint32_t bf[2];
                bf[0] = *reinterpret_cast<const uint32_t*>(vr);
                bf[1] = *reinterpret_cast<const uint32_t*>(vr + 8);
                mma_f16(o[0][nt], paf[0][k2], bf);
                mma_f16(o[1][nt], paf[1][k2], bf);
            }
        }

        asm volatile("cp.async.wait_group 0;\n" ::: "memory");
        __syncthreads();
    }

#pragma unroll
    for (int mt = 0; mt < 2; mt++)
#pragma unroll
        for (int hf = 0; hf < 2; hf++) {
            float r = l_[mt][hf];
            r += __shfl_xor_sync(0xffffffffu, r, 1);
            r += __shfl_xor_sync(0xffffffffu, r, 2);
            l_[mt][hf] = r;
        }

    float lam = side ? log1pf(__expf(lambda_p[h])) : 1.f;
    float inv[2][2] = {{lam / l_[0][0], lam / l_[0][1]},
                       {lam / l_[1][0], lam / l_[1][1]}};

    __half* dst = g_odh + ((size_t)side * M_ROWS + (size_t)(b * N_ + ph * 32)) * 768 + h * 64;
#pragma unroll
    for (int mt = 0; mt < 2; mt++)
#pragma unroll
        for (int nt = 0; nt < 8; nt++) {
            int r0 = mt * 16 + gid, r1 = r0 + 8, cc = nt * 8 + 2 * tig;
            *reinterpret_cast<uint32_t*>(dst + (size_t)r0 * 768 + cc) =
                h2pack(o[mt][nt][0] * inv[mt][0], o[mt][nt][1] * inv[mt][0]);
            *reinterpret_cast<uint32_t*>(dst + (size_t)r1 * 768 + cc) =
                h2pack(o[mt][nt][2] * inv[mt][1], o[mt][nt][3] * inv[mt][1]);
        }
}

// ---------------------------------------------------------------------------
// Combine: ctxh = fp16(O1 - O2_scaled). 4 halves per thread.
// ---------------------------------------------------------------------------
#define CTX_Q (M_ROWS * DIM_ / 4)   // 786432

__global__ __launch_bounds__(256)
void combine_o()
{
    int idx = blockIdx.x * 256 + threadIdx.x;
    if (idx >= CTX_Q) return;
    uint2 a = reinterpret_cast<const uint2*>(g_odh)[idx];
    uint2 c = reinterpret_cast<const uint2*>(g_odh + (size_t)M_ROWS * DIM_)[idx];
    float2 a0 = __half22float2(*reinterpret_cast<__half2*>(&a.x));
    float2 a1 = __half22float2(*reinterpret_cast<__half2*>(&a.y));
    float2 c0 = __half22float2(*reinterpret_cast<__half2*>(&c.x));
    float2 c1 = __half22float2(*reinterpret_cast<__half2*>(&c.y));
    uint2 r;
    r.x = h2pack(a0.x - c0.x, a0.y - c0.y);
    r.y = h2pack(a1.x - c1.x, a1.y - c1.y);
    reinterpret_cast<uint2*>(g_ctxh)[idx] = r;
}

// ---------------------------------------------------------------------------
// Launch
// ---------------------------------------------------------------------------
extern "C" void kernel_launch(void* const* d_in, const int* in_sizes, int n_in,
                              void* d_out, int out_size)
{
    const float* x      = (const float*)d_in[0];
    const float* Wq     = (const float*)d_in[1];
    const float* Wk     = (const float*)d_in[2];
    const float* Wv1    = (const float*)d_in[3];
    const float* Wv2    = (const float*)d_in[4];
    const float* lam_p  = (const float*)d_in[5];
    const float* Wo     = (const float*)d_in[6];
    const float* bo     = (const float*)d_in[7];
    float* out = (float*)d_out;

    __half *gxh, *gwh, *gwoh, *ctxh, *proj;
    cudaGetSymbolAddress((void**)&gxh,  g_xh);
    cudaGetSymbolAddress((void**)&gwh,  g_wh);
    cudaGetSymbolAddress((void**)&gwoh, g_woh);
    cudaGetSymbolAddress((void**)&proj, g_proj);
    cudaGetSymbolAddress((void**)&ctxh, g_ctxh);

    cudaFuncSetAttribute(gemm_f16<true>,  cudaFuncAttributeMaxDynamicSharedMemorySize, GEMM_SMEM_BYTES);
    cudaFuncSetAttribute(gemm_f16<false>, cudaFuncAttributeMaxDynamicSharedMemorySize, GEMM_SMEM_BYTES);
    cudaFuncSetAttribute(attn_tc, cudaFuncAttributeMaxDynamicSharedMemorySize, ATT_SMEM_BYTES);

    // fp16 conversion + weight concat
    prep_f16<<<(PREP_TOTAL + 255) / 256, 256>>>(x, Wq, Wk, Wv1, Wv2, Wo);

    // fused projections: fp16 GEMM [4096 x 2560 x 768] -> fp16 g_proj
    gemm_f16<true><<<dim3(PROJ_N / TBN, M_ROWS / TBM), 256, GEMM_SMEM_BYTES>>>(
        gxh, gwh, nullptr, proj, M_ROWS, PROJ_N, DIM_);

    // RoPE + qk-norm -> fp16 g_qkh
    {
        int vec = M_ROWS * 32;
        rope_norm<<<(vec * 32 + 255) / 256, 256>>>(vec);
    }

    // V transpose -> g_vt
    v_transpose<<<1024, 256>>>();

    // fp16 tensor-core windowed attention -> fp16 g_odh
    attn_tc<<<B_ * KV_ * 2 * SIDE_, 96, ATT_SMEM_BYTES>>>(lam_p);

    // differential combine -> fp16 ctx
    combine_o<<<(CTX_Q + 255) / 256, 256>>>();

    // output projection + bias (fp32 out)
    gemm_f16<false><<<dim3(DIM_ / TBN, M_ROWS / TBM), 256, GEMM_SMEM_BYTES>>>(
        ctxh, gwoh, bo, out, M_ROWS, DIM_, DIM_);
}